// round 1
// baseline (speedup 1.0000x reference)
#include <cuda_runtime.h>
#include <math.h>

#define BATCH 16
#define CH    256
#define NPIX  16384
#define HEADS 8
#define DH    32
#define NMEM  4
#define SCALE_Q 0.5f
#define LN_EPS 1e-5f

// ---------------- scratch (device globals; no allocations allowed) ----------------
__device__ float g_mean[BATCH*CH];
__device__ float g_rstd[BATCH*CH];
__device__ float g_S[BATCH*HEADS*DH*DH];   // [b][h][d][e]  sum_n exp(k[d,n])*v[e,n]
__device__ float g_Z[BATCH*HEADS*DH];      // [b][h][d]     sum_n exp(k[d,n])
__device__ float g_wf[BATCH*CH*CH];        // [b][c][h*32+d] fused W_out x ctx

// ---------------- kernel 0: zero accumulators (graph-replay safe) ----------------
__global__ void k_zero() {
    int i = blockIdx.x * 256 + threadIdx.x;
    if (i < BATCH*HEADS*DH*DH) g_S[i] = 0.f;
    if (i < BATCH*HEADS*DH)    g_Z[i] = 0.f;
}

// ---------------- kernel 1: per (b,c) spatial mean / rstd ----------------
__global__ __launch_bounds__(256) void k_stats(const float* __restrict__ x) {
    int bc = blockIdx.x;                       // 0..4095
    const float4* p = (const float4*)(x + (size_t)bc * NPIX);
    float s = 0.f, ss = 0.f;
    for (int i = threadIdx.x; i < NPIX/4; i += 256) {
        float4 v = p[i];
        s  += v.x + v.y + v.z + v.w;
        ss += v.x*v.x + v.y*v.y + v.z*v.z + v.w*v.w;
    }
    __shared__ float rs[256], rq[256];
    rs[threadIdx.x] = s; rq[threadIdx.x] = ss;
    __syncthreads();
    for (int o = 128; o > 0; o >>= 1) {
        if (threadIdx.x < o) {
            rs[threadIdx.x] += rs[threadIdx.x + o];
            rq[threadIdx.x] += rq[threadIdx.x + o];
        }
        __syncthreads();
    }
    if (threadIdx.x == 0) {
        float m   = rs[0] * (1.f / NPIX);
        float var = rq[0] * (1.f / NPIX) - m * m;
        g_mean[bc] = m;
        g_rstd[bc] = rsqrtf(var + LN_EPS);
    }
}

// ---------------- kernel 2: fused KV GEMM + exp + outer-product accumulate ---------
// Per block: batch b, 32-pixel tile. GEMM [512 kv-rows x 32 px], K=256,
// then S_h[d][e] += sum_px exp(k)*v, Z_h[d] += sum_px exp(k); atomicAdd to global.
// dyn smem floats: wsm 8*516=4128, xn 8*32=256, kexp 256*33=8448, vsm 8448 -> 85120 B
#define KV_SMEM_BYTES ((4128 + 256 + 8448 + 8448) * 4)

__global__ __launch_bounds__(256, 2) void k_kv(const float* __restrict__ x,
                                               const float* __restrict__ w_qkv) {
    extern __shared__ float sm[];
    float* wsm  = sm;
    float* xnsm = wsm + 4128;
    float* kexp = xnsm + 256;
    float* vsm  = kexp + 8448;

    const int b  = blockIdx.y;
    const int pt = blockIdx.x;
    const int t  = threadIdx.x;
    const int r0 = (t >> 2) * 8;   // 0..504 (kv row micro-tile base)
    const int p0 = (t & 3) * 8;    // 0..24  (pixel micro-tile base)

    const float* xb  = x + (size_t)b * CH * NPIX + (size_t)pt * 32;
    const float* wkv = w_qkv + 256 * CH;   // rows 256..767 = K then V

    float acc[8][8];
    #pragma unroll
    for (int i = 0; i < 8; i++)
        #pragma unroll
        for (int j = 0; j < 8; j++) acc[i][j] = 0.f;

    const int kch = t >> 5;   // xn loader: channel-within-tile
    const int kp  = t & 31;   // xn loader: pixel

    for (int c0 = 0; c0 < CH; c0 += 8) {
        __syncthreads();
        #pragma unroll
        for (int i = 0; i < 4; i++) {
            int idx = t + i * 256;            // 0..1023 float4 slots
            int r   = idx >> 1;               // 0..511
            int cq  = (idx & 1) * 4;
            float4 w = *(const float4*)(wkv + (size_t)r * CH + c0 + cq);
            wsm[(cq+0)*516 + r] = w.x;
            wsm[(cq+1)*516 + r] = w.y;
            wsm[(cq+2)*516 + r] = w.z;
            wsm[(cq+3)*516 + r] = w.w;
        }
        {
            int ch = c0 + kch;
            float xv = xb[(size_t)ch * NPIX + kp];
            xnsm[kch*32 + kp] = (xv - g_mean[b*CH + ch]) * g_rstd[b*CH + ch];
        }
        __syncthreads();
        #pragma unroll
        for (int k = 0; k < 8; k++) {
            float wf[8], xf[8];
            *(float4*)&wf[0] = *(const float4*)&wsm[k*516 + r0];
            *(float4*)&wf[4] = *(const float4*)&wsm[k*516 + r0 + 4];
            *(float4*)&xf[0] = *(const float4*)&xnsm[k*32 + p0];
            *(float4*)&xf[4] = *(const float4*)&xnsm[k*32 + p0 + 4];
            #pragma unroll
            for (int i = 0; i < 8; i++)
                #pragma unroll
                for (int j = 0; j < 8; j++)
                    acc[i][j] = fmaf(wf[i], xf[j], acc[i][j]);
        }
    }

    // stash exp(k) and v in smem (padded stride 33 -> conflict-free column reads)
    if (r0 < 256) {
        #pragma unroll
        for (int i = 0; i < 8; i++) {
            int r = r0 + i;
            #pragma unroll
            for (int j = 0; j < 8; j++)
                kexp[r*33 + p0 + j] = expf(acc[i][j]);
        }
    } else {
        #pragma unroll
        for (int i = 0; i < 8; i++) {
            int r = r0 + i - 256;
            #pragma unroll
            for (int j = 0; j < 8; j++)
                vsm[r*33 + p0 + j] = acc[i][j];
        }
    }
    __syncthreads();

    // outer product: thread = (head h, dim d); 32 e-accumulators over 32 px
    const int h = t >> 5, d = t & 31;
    float sacc[32];
    #pragma unroll
    for (int e = 0; e < 32; e++) sacc[e] = 0.f;
    float z = 0.f;
    const float* krow = kexp + (h*32 + d) * 33;
    const float* vb   = vsm  + (h*32) * 33;
    for (int p = 0; p < 32; p++) {
        float ke = krow[p];
        z += ke;
        #pragma unroll
        for (int e = 0; e < 32; e++)
            sacc[e] = fmaf(ke, vb[e*33 + p], sacc[e]);
    }
    float* Sp = g_S + ((size_t)(b*HEADS + h)*DH + d) * DH;
    #pragma unroll
    for (int e = 0; e < 32; e++) atomicAdd(&Sp[e], sacc[e]);
    atomicAdd(&g_Z[(b*HEADS + h)*DH + d], z);
}

// ---------------- kernel 3: finalize context + fold into W_out -> g_wf -------------
// ctx[d][e] = (S + sum_m exp(mk[d,m]) mv[e,m]) / (Z + sum_m exp(mk[d,m]))
// Wf[b][c][h*32+d] = sum_e w_out[c][h*32+e] * ctx[d][e]
__global__ __launch_bounds__(256) void k_wf(const float* __restrict__ mem_kv,
                                            const float* __restrict__ w_out) {
    __shared__ float ctxsm[DH*DH];     // [d][e]
    __shared__ float wsm[CH*33];       // [c][e], padded
    const int h = blockIdx.x, b = blockIdx.y;
    const int t = threadIdx.x;

    {
        int d  = t >> 3;
        int e0 = (t & 7) * 4;
        float ekm[NMEM];
        float zm = 0.f;
        #pragma unroll
        for (int m = 0; m < NMEM; m++) {
            float mk = mem_kv[(h*DH + d)*NMEM + m];
            ekm[m] = expf(mk);
            zm += ekm[m];
        }
        float zden = g_Z[(b*HEADS + h)*DH + d] + zm;
        float inv  = 1.f / zden;
        #pragma unroll
        for (int j = 0; j < 4; j++) {
            int e = e0 + j;
            float s = g_S[((size_t)(b*HEADS + h)*DH + d)*DH + e];
            float smem_c = 0.f;
            #pragma unroll
            for (int m = 0; m < NMEM; m++) {
                float mv = mem_kv[HEADS*DH*NMEM + (h*DH + e)*NMEM + m];
                smem_c = fmaf(ekm[m], mv, smem_c);
            }
            ctxsm[d*DH + e] = (s + smem_c) * inv;
        }
    }
    #pragma unroll
    for (int i = 0; i < 8; i++) {
        int idx = t + i * 256;
        int c   = idx >> 3;
        int eq  = (idx & 7) * 4;
        float4 w = *(const float4*)(w_out + (size_t)c * CH + h*DH + eq);
        wsm[c*33 + eq + 0] = w.x;
        wsm[c*33 + eq + 1] = w.y;
        wsm[c*33 + eq + 2] = w.z;
        wsm[c*33 + eq + 3] = w.w;
    }
    __syncthreads();

    float acc[DH];
    #pragma unroll
    for (int d = 0; d < DH; d++) acc[d] = 0.f;
    for (int e = 0; e < DH; e++) {
        float w = wsm[t*33 + e];
        #pragma unroll
        for (int d = 0; d < DH; d++)
            acc[d] = fmaf(w, ctxsm[d*DH + e], acc[d]);
    }
    float* dst = g_wf + ((size_t)b*CH + t)*CH + h*DH;
    #pragma unroll
    for (int d = 0; d < DH; d++) dst[d] = acc[d];
}

// ---------------- kernel 4: q GEMM -> head softmax -> Wf GEMM -> LN -> residual ----
// dyn smem floats: xn 256*36=9216, qsm 9216, wsm 8*260=2080 -> 82048 B
#define XP 36
#define OUT_SMEM_BYTES ((9216 + 9216 + 2080) * 4)

__global__ __launch_bounds__(256, 2) void k_out(const float* __restrict__ x,
                                                const float* __restrict__ w_qkv,
                                                const float* __restrict__ b_out,
                                                const float* __restrict__ ln_g,
                                                float* __restrict__ out) {
    extern __shared__ float sm[];
    float* xnsm = sm;                 // [c][px] stride XP
    float* qsm  = xnsm + CH*XP;       // q / qs / y (reused)
    float* wsm  = qsm  + CH*XP;       // [k][row] stride 260
    __shared__ float colsum[8][32], colsq[8][32], mcol[32], rcol[32];

    const int b  = blockIdx.y, pt = blockIdx.x;
    const int t  = threadIdx.x;
    const int p  = t & 31, cb = t >> 5;

    const float* xb = x + (size_t)b * CH * NPIX + (size_t)pt * 32;

    #pragma unroll 4
    for (int i = 0; i < 32; i++) {
        int c = cb + i * 8;
        float xv = xb[(size_t)c * NPIX + p];
        xnsm[c*XP + p] = (xv - g_mean[b*CH + c]) * g_rstd[b*CH + c];
    }

    const int r0 = (t >> 3) * 8;   // output-row micro base
    const int p0 = (t & 7) * 4;    // pixel micro base
    float acc[8][4];
    #pragma unroll
    for (int i = 0; i < 8; i++)
        #pragma unroll
        for (int j = 0; j < 4; j++) acc[i][j] = 0.f;

    // ---- GEMM 1: q[o][px] = W_q[o][c] * xn[c][px], o = h*32+d ----
    for (int c0 = 0; c0 < CH; c0 += 8) {
        __syncthreads();
        #pragma unroll
        for (int i = 0; i < 2; i++) {
            int idx = t + i * 256;
            int r   = idx >> 1;
            int cq  = (idx & 1) * 4;
            float4 w = *(const float4*)(w_qkv + (size_t)r * CH + c0 + cq);
            wsm[(cq+0)*260 + r] = w.x;
            wsm[(cq+1)*260 + r] = w.y;
            wsm[(cq+2)*260 + r] = w.z;
            wsm[(cq+3)*260 + r] = w.w;
        }
        __syncthreads();
        #pragma unroll
        for (int k = 0; k < 8; k++) {
            float wf[8], xf[4];
            *(float4*)&wf[0] = *(const float4*)&wsm[k*260 + r0];
            *(float4*)&wf[4] = *(const float4*)&wsm[k*260 + r0 + 4];
            *(float4*)&xf[0] = *(const float4*)&xnsm[(c0+k)*XP + p0];
            #pragma unroll
            for (int i = 0; i < 8; i++)
                #pragma unroll
                for (int j = 0; j < 4; j++)
                    acc[i][j] = fmaf(wf[i], xf[j], acc[i][j]);
        }
    }
    __syncthreads();
    #pragma unroll
    for (int i = 0; i < 8; i++)
        #pragma unroll
        for (int j = 0; j < 4; j++)
            qsm[(r0+i)*XP + p0 + j] = acc[i][j];
    __syncthreads();

    // ---- per-(head,pixel) softmax over d, scaled ----
    {
        float* qc = qsm + (size_t)(cb * 32) * XP + p;   // head = cb, pixel = p
        float vals[32];
        float mx = -1e30f;
        #pragma unroll
        for (int dd = 0; dd < 32; dd++) { vals[dd] = qc[dd*XP]; mx = fmaxf(mx, vals[dd]); }
        float s = 0.f;
        #pragma unroll
        for (int dd = 0; dd < 32; dd++) { vals[dd] = expf(vals[dd] - mx); s += vals[dd]; }
        float inv = SCALE_Q / s;
        #pragma unroll
        for (int dd = 0; dd < 32; dd++) qc[dd*XP] = vals[dd] * inv;
    }
    __syncthreads();

    // ---- GEMM 2: y[c][px] = Wf[b][c][hd] * qs[hd][px] ----
    #pragma unroll
    for (int i = 0; i < 8; i++)
        #pragma unroll
        for (int j = 0; j < 4; j++) acc[i][j] = 0.f;
    const float* wf_b = g_wf + (size_t)b * CH * CH;
    for (int c0 = 0; c0 < CH; c0 += 8) {
        __syncthreads();
        #pragma unroll
        for (int i = 0; i < 2; i++) {
            int idx = t + i * 256;
            int r   = idx >> 1;
            int cq  = (idx & 1) * 4;
            float4 w = *(const float4*)(wf_b + (size_t)r * CH + c0 + cq);
            wsm[(cq+0)*260 + r] = w.x;
            wsm[(cq+1)*260 + r] = w.y;
            wsm[(cq+2)*260 + r] = w.z;
            wsm[(cq+3)*260 + r] = w.w;
        }
        __syncthreads();
        #pragma unroll
        for (int k = 0; k < 8; k++) {
            float wf[8], xf[4];
            *(float4*)&wf[0] = *(const float4*)&wsm[k*260 + r0];
            *(float4*)&wf[4] = *(const float4*)&wsm[k*260 + r0 + 4];
            *(float4*)&xf[0] = *(const float4*)&qsm[(c0+k)*XP + p0];
            #pragma unroll
            for (int i = 0; i < 8; i++)
                #pragma unroll
                for (int j = 0; j < 4; j++)
                    acc[i][j] = fmaf(wf[i], xf[j], acc[i][j]);
        }
    }
    __syncthreads();   // all qsm reads done; safe to overwrite with y
    #pragma unroll
    for (int i = 0; i < 8; i++) {
        float bo = b_out[r0 + i];
        #pragma unroll
        for (int j = 0; j < 4; j++)
            qsm[(r0+i)*XP + p0 + j] = acc[i][j] + bo;
    }
    __syncthreads();

    // ---- channel LayerNorm per pixel + residual ----
    {
        float ps = 0.f, pq = 0.f;
        for (int i = 0; i < 32; i++) {
            float v = qsm[(cb*32 + i)*XP + p];
            ps += v; pq += v * v;
        }
        colsum[cb][p] = ps; colsq[cb][p] = pq;
    }
    __syncthreads();
    if (t < 32) {
        float s = 0.f, q2 = 0.f;
        #pragma unroll
        for (int sg = 0; sg < 8; sg++) { s += colsum[sg][t]; q2 += colsq[sg][t]; }
        float m   = s * (1.f / 256.f);
        float var = q2 * (1.f / 256.f) - m * m;
        mcol[t] = m;
        rcol[t] = rsqrtf(var + LN_EPS);
    }
    __syncthreads();
    float* ob = out + (size_t)b * CH * NPIX + (size_t)pt * 32;
    #pragma unroll 4
    for (int i = 0; i < 32; i++) {
        int c = cb + i * 8;
        float v = (qsm[c*XP + p] - mcol[p]) * rcol[p] * ln_g[c] + xnsm[c*XP + p];
        ob[(size_t)c * NPIX + p] = v;
    }
}

// ---------------- launch ----------------
extern "C" void kernel_launch(void* const* d_in, const int* in_sizes, int n_in,
                              void* d_out, int out_size) {
    const float* x      = (const float*)d_in[0];
    const float* w_qkv  = (const float*)d_in[1];
    const float* mem_kv = (const float*)d_in[2];
    const float* w_out  = (const float*)d_in[3];
    const float* b_out  = (const float*)d_in[4];
    const float* ln_g   = (const float*)d_in[5];
    float* out = (float*)d_out;

    cudaFuncSetAttribute(k_kv,  cudaFuncAttributeMaxDynamicSharedMemorySize, KV_SMEM_BYTES);
    cudaFuncSetAttribute(k_out, cudaFuncAttributeMaxDynamicSharedMemorySize, OUT_SMEM_BYTES);

    k_zero<<<512, 256>>>();
    k_stats<<<BATCH * CH, 256>>>(x);
    k_kv<<<dim3(NPIX/32, BATCH), 256, KV_SMEM_BYTES>>>(x, w_qkv);
    k_wf<<<dim3(HEADS, BATCH), 256>>>(mem_kv, w_out);
    k_out<<<dim3(NPIX/32, BATCH), 256, OUT_SMEM_BYTES>>>(x, w_qkv, b_out, ln_g, out);
}

// round 2
// speedup vs baseline: 1.0001x; 1.0001x over previous
#include <cuda_runtime.h>
#include <math.h>

#define BATCH 16
#define CH    256
#define NPIX  16384
#define HEADS 8
#define DH    32
#define NMEM  4
#define SCALE_Q 0.5f
#define LN_EPS 1e-5f

// ---------------- scratch (device globals; no allocations allowed) ----------------
__device__ float g_mean[BATCH*CH];
__device__ float g_rstd[BATCH*CH];
__device__ float g_S[BATCH*HEADS*DH*DH];   // [b][h][d][e]  sum_n exp(k[d,n])*v[e,n]
__device__ float g_Z[BATCH*HEADS*DH];      // [b][h][d]     sum_n exp(k[d,n])
__device__ float g_wf[BATCH*CH*CH];        // [b][c][h*32+d] fused W_out x ctx

// ---------------- kernel 0: zero accumulators (graph-replay safe) ----------------
__global__ void k_zero() {
    int i = blockIdx.x * 256 + threadIdx.x;
    if (i < BATCH*HEADS*DH*DH) g_S[i] = 0.f;
    if (i < BATCH*HEADS*DH)    g_Z[i] = 0.f;
}

// ---------------- kernel 1: per (b,c) spatial mean / rstd ----------------
__global__ __launch_bounds__(256) void k_stats(const float* __restrict__ x) {
    int bc = blockIdx.x;                       // 0..4095
    const float4* p = (const float4*)(x + (size_t)bc * NPIX);
    float s = 0.f, ss = 0.f;
    for (int i = threadIdx.x; i < NPIX/4; i += 256) {
        float4 v = p[i];
        s  += v.x + v.y + v.z + v.w;
        ss += v.x*v.x + v.y*v.y + v.z*v.z + v.w*v.w;
    }
    __shared__ float rs[256], rq[256];
    rs[threadIdx.x] = s; rq[threadIdx.x] = ss;
    __syncthreads();
    for (int o = 128; o > 0; o >>= 1) {
        if (threadIdx.x < o) {
            rs[threadIdx.x] += rs[threadIdx.x + o];
            rq[threadIdx.x] += rq[threadIdx.x + o];
        }
        __syncthreads();
    }
    if (threadIdx.x == 0) {
        float m   = rs[0] * (1.f / NPIX);
        float var = rq[0] * (1.f / NPIX) - m * m;
        g_mean[bc] = m;
        g_rstd[bc] = rsqrtf(var + LN_EPS);
    }
}

// ---------------- kernel 2: fused KV GEMM + exp + outer-product accumulate ---------
// Per block: batch b, 32-pixel tile. GEMM [512 kv-rows x 32 px], K=256,
// then S_h[d][e] += sum_px exp(k)*v, Z_h[d] += sum_px exp(k); atomicAdd to global.
// dyn smem floats: wsm 8*516=4128, xn 8*32=256, kexp 256*33=8448, vsm 8448 -> 85120 B
#define KV_SMEM_BYTES ((4128 + 256 + 8448 + 8448) * 4)

__global__ __launch_bounds__(256, 2) void k_kv(const float* __restrict__ x,
                                               const float* __restrict__ w_qkv) {
    extern __shared__ float sm[];
    float* wsm  = sm;
    float* xnsm = wsm + 4128;
    float* kexp = xnsm + 256;
    float* vsm  = kexp + 8448;

    const int b  = blockIdx.y;
    const int pt = blockIdx.x;
    const int t  = threadIdx.x;
    const int r0 = (t >> 2) * 8;   // 0..504 (kv row micro-tile base)
    const int p0 = (t & 3) * 8;    // 0..24  (pixel micro-tile base)

    const float* xb  = x + (size_t)b * CH * NPIX + (size_t)pt * 32;
    const float* wkv = w_qkv + 256 * CH;   // rows 256..767 = K then V

    float acc[8][8];
    #pragma unroll
    for (int i = 0; i < 8; i++)
        #pragma unroll
        for (int j = 0; j < 8; j++) acc[i][j] = 0.f;

    const int kch = t >> 5;   // xn loader: channel-within-tile
    const int kp  = t & 31;   // xn loader: pixel

    for (int c0 = 0; c0 < CH; c0 += 8) {
        __syncthreads();
        #pragma unroll
        for (int i = 0; i < 4; i++) {
            int idx = t + i * 256;            // 0..1023 float4 slots
            int r   = idx >> 1;               // 0..511
            int cq  = (idx & 1) * 4;
            float4 w = *(const float4*)(wkv + (size_t)r * CH + c0 + cq);
            wsm[(cq+0)*516 + r] = w.x;
            wsm[(cq+1)*516 + r] = w.y;
            wsm[(cq+2)*516 + r] = w.z;
            wsm[(cq+3)*516 + r] = w.w;
        }
        {
            int ch = c0 + kch;
            float xv = xb[(size_t)ch * NPIX + kp];
            xnsm[kch*32 + kp] = (xv - g_mean[b*CH + ch]) * g_rstd[b*CH + ch];
        }
        __syncthreads();
        #pragma unroll
        for (int k = 0; k < 8; k++) {
            float wf[8], xf[8];
            *(float4*)&wf[0] = *(const float4*)&wsm[k*516 + r0];
            *(float4*)&wf[4] = *(const float4*)&wsm[k*516 + r0 + 4];
            *(float4*)&xf[0] = *(const float4*)&xnsm[k*32 + p0];
            *(float4*)&xf[4] = *(const float4*)&xnsm[k*32 + p0 + 4];
            #pragma unroll
            for (int i = 0; i < 8; i++)
                #pragma unroll
                for (int j = 0; j < 8; j++)
                    acc[i][j] = fmaf(wf[i], xf[j], acc[i][j]);
        }
    }

    // stash exp(k) and v in smem (padded stride 33 -> conflict-free column reads)
    if (r0 < 256) {
        #pragma unroll
        for (int i = 0; i < 8; i++) {
            int r = r0 + i;
            #pragma unroll
            for (int j = 0; j < 8; j++)
                kexp[r*33 + p0 + j] = expf(acc[i][j]);
        }
    } else {
        #pragma unroll
        for (int i = 0; i < 8; i++) {
            int r = r0 + i - 256;
            #pragma unroll
            for (int j = 0; j < 8; j++)
                vsm[r*33 + p0 + j] = acc[i][j];
        }
    }
    __syncthreads();

    // outer product: thread = (head h, dim d); 32 e-accumulators over 32 px
    const int h = t >> 5, d = t & 31;
    float sacc[32];
    #pragma unroll
    for (int e = 0; e < 32; e++) sacc[e] = 0.f;
    float z = 0.f;
    const float* krow = kexp + (h*32 + d) * 33;
    const float* vb   = vsm  + (h*32) * 33;
    for (int p = 0; p < 32; p++) {
        float ke = krow[p];
        z += ke;
        #pragma unroll
        for (int e = 0; e < 32; e++)
            sacc[e] = fmaf(ke, vb[e*33 + p], sacc[e]);
    }
    float* Sp = g_S + ((size_t)(b*HEADS + h)*DH + d) * DH;
    #pragma unroll
    for (int e = 0; e < 32; e++) atomicAdd(&Sp[e], sacc[e]);
    atomicAdd(&g_Z[(b*HEADS + h)*DH + d], z);
}

// ---------------- kernel 3: finalize context + fold into W_out -> g_wf -------------
// ctx[d][e] = (S + sum_m exp(mk[d,m]) mv[e,m]) / (Z + sum_m exp(mk[d,m]))
// Wf[b][c][h*32+d] = sum_e w_out[c][h*32+e] * ctx[d][e]
__global__ __launch_bounds__(256) void k_wf(const float* __restrict__ mem_kv,
                                            const float* __restrict__ w_out) {
    __shared__ float ctxsm[DH*DH];     // [d][e]
    __shared__ float wsm[CH*33];       // [c][e], padded
    const int h = blockIdx.x, b = blockIdx.y;
    const int t = threadIdx.x;

    {
        int d  = t >> 3;
        int e0 = (t & 7) * 4;
        float ekm[NMEM];
        float zm = 0.f;
        #pragma unroll
        for (int m = 0; m < NMEM; m++) {
            float mk = mem_kv[(h*DH + d)*NMEM + m];
            ekm[m] = expf(mk);
            zm += ekm[m];
        }
        float zden = g_Z[(b*HEADS + h)*DH + d] + zm;
        float inv  = 1.f / zden;
        #pragma unroll
        for (int j = 0; j < 4; j++) {
            int e = e0 + j;
            float s = g_S[((size_t)(b*HEADS + h)*DH + d)*DH + e];
            float smem_c = 0.f;
            #pragma unroll
            for (int m = 0; m < NMEM; m++) {
                float mv = mem_kv[HEADS*DH*NMEM + (h*DH + e)*NMEM + m];
                smem_c = fmaf(ekm[m], mv, smem_c);
            }
            ctxsm[d*DH + e] = (s + smem_c) * inv;
        }
    }
    #pragma unroll
    for (int i = 0; i < 8; i++) {
        int idx = t + i * 256;
        int c   = idx >> 3;
        int eq  = (idx & 7) * 4;
        float4 w = *(const float4*)(w_out + (size_t)c * CH + h*DH + eq);
        wsm[c*33 + eq + 0] = w.x;
        wsm[c*33 + eq + 1] = w.y;
        wsm[c*33 + eq + 2] = w.z;
        wsm[c*33 + eq + 3] = w.w;
    }
    __syncthreads();

    float acc[DH];
    #pragma unroll
    for (int d = 0; d < DH; d++) acc[d] = 0.f;
    for (int e = 0; e < DH; e++) {
        float w = wsm[t*33 + e];
        #pragma unroll
        for (int d = 0; d < DH; d++)
            acc[d] = fmaf(w, ctxsm[d*DH + e], acc[d]);
    }
    float* dst = g_wf + ((size_t)b*CH + t)*CH + h*DH;
    #pragma unroll
    for (int d = 0; d < DH; d++) dst[d] = acc[d];
}

// ---------------- kernel 4: q GEMM -> head softmax -> Wf GEMM -> LN -> residual ----
// dyn smem floats: xn 256*36=9216, qsm 9216, wsm 8*260=2080 -> 82048 B
#define XP 36
#define OUT_SMEM_BYTES ((9216 + 9216 + 2080) * 4)

__global__ __launch_bounds__(256, 2) void k_out(const float* __restrict__ x,
                                                const float* __restrict__ w_qkv,
                                                const float* __restrict__ b_out,
                                                const float* __restrict__ ln_g,
                                                float* __restrict__ out) {
    extern __shared__ float sm[];
    float* xnsm = sm;                 // [c][px] stride XP
    float* qsm  = xnsm + CH*XP;       // q / qs / y (reused)
    float* wsm  = qsm  + CH*XP;       // [k][row] stride 260
    __shared__ float colsum[8][32], colsq[8][32], mcol[32], rcol[32];

    const int b  = blockIdx.y, pt = blockIdx.x;
    const int t  = threadIdx.x;
    const int p  = t & 31, cb = t >> 5;

    const float* xb = x + (size_t)b * CH * NPIX + (size_t)pt * 32;

    #pragma unroll 4
    for (int i = 0; i < 32; i++) {
        int c = cb + i * 8;
        float xv = xb[(size_t)c * NPIX + p];
        xnsm[c*XP + p] = (xv - g_mean[b*CH + c]) * g_rstd[b*CH + c];
    }

    const int r0 = (t >> 3) * 8;   // output-row micro base
    const int p0 = (t & 7) * 4;    // pixel micro base
    float acc[8][4];
    #pragma unroll
    for (int i = 0; i < 8; i++)
        #pragma unroll
        for (int j = 0; j < 4; j++) acc[i][j] = 0.f;

    // ---- GEMM 1: q[o][px] = W_q[o][c] * xn[c][px], o = h*32+d ----
    for (int c0 = 0; c0 < CH; c0 += 8) {
        __syncthreads();
        #pragma unroll
        for (int i = 0; i < 2; i++) {
            int idx = t + i * 256;
            int r   = idx >> 1;
            int cq  = (idx & 1) * 4;
            float4 w = *(const float4*)(w_qkv + (size_t)r * CH + c0 + cq);
            wsm[(cq+0)*260 + r] = w.x;
            wsm[(cq+1)*260 + r] = w.y;
            wsm[(cq+2)*260 + r] = w.z;
            wsm[(cq+3)*260 + r] = w.w;
        }
        __syncthreads();
        #pragma unroll
        for (int k = 0; k < 8; k++) {
            float wf[8], xf[4];
            *(float4*)&wf[0] = *(const float4*)&wsm[k*260 + r0];
            *(float4*)&wf[4] = *(const float4*)&wsm[k*260 + r0 + 4];
            *(float4*)&xf[0] = *(const float4*)&xnsm[(c0+k)*XP + p0];
            #pragma unroll
            for (int i = 0; i < 8; i++)
                #pragma unroll
                for (int j = 0; j < 4; j++)
                    acc[i][j] = fmaf(wf[i], xf[j], acc[i][j]);
        }
    }
    __syncthreads();
    #pragma unroll
    for (int i = 0; i < 8; i++)
        #pragma unroll
        for (int j = 0; j < 4; j++)
            qsm[(r0+i)*XP + p0 + j] = acc[i][j];
    __syncthreads();

    // ---- per-(head,pixel) softmax over d, scaled ----
    {
        float* qc = qsm + (size_t)(cb * 32) * XP + p;   // head = cb, pixel = p
        float vals[32];
        float mx = -1e30f;
        #pragma unroll
        for (int dd = 0; dd < 32; dd++) { vals[dd] = qc[dd*XP]; mx = fmaxf(mx, vals[dd]); }
        float s = 0.f;
        #pragma unroll
        for (int dd = 0; dd < 32; dd++) { vals[dd] = expf(vals[dd] - mx); s += vals[dd]; }
        float inv = SCALE_Q / s;
        #pragma unroll
        for (int dd = 0; dd < 32; dd++) qc[dd*XP] = vals[dd] * inv;
    }
    __syncthreads();

    // ---- GEMM 2: y[c][px] = Wf[b][c][hd] * qs[hd][px] ----
    #pragma unroll
    for (int i = 0; i < 8; i++)
        #pragma unroll
        for (int j = 0; j < 4; j++) acc[i][j] = 0.f;
    const float* wf_b = g_wf + (size_t)b * CH * CH;
    for (int c0 = 0; c0 < CH; c0 += 8) {
        __syncthreads();
        #pragma unroll
        for (int i = 0; i < 2; i++) {
            int idx = t + i * 256;
            int r   = idx >> 1;
            int cq  = (idx & 1) * 4;
            float4 w = *(const float4*)(wf_b + (size_t)r * CH + c0 + cq);
            wsm[(cq+0)*260 + r] = w.x;
            wsm[(cq+1)*260 + r] = w.y;
            wsm[(cq+2)*260 + r] = w.z;
            wsm[(cq+3)*260 + r] = w.w;
        }
        __syncthreads();
        #pragma unroll
        for (int k = 0; k < 8; k++) {
            float wf[8], xf[4];
            *(float4*)&wf[0] = *(const float4*)&wsm[k*260 + r0];
            *(float4*)&wf[4] = *(const float4*)&wsm[k*260 + r0 + 4];
            *(float4*)&xf[0] = *(const float4*)&qsm[(c0+k)*XP + p0];
            #pragma unroll
            for (int i = 0; i < 8; i++)
                #pragma unroll
                for (int j = 0; j < 4; j++)
                    acc[i][j] = fmaf(wf[i], xf[j], acc[i][j]);
        }
    }
    __syncthreads();   // all qsm reads done; safe to overwrite with y
    #pragma unroll
    for (int i = 0; i < 8; i++) {
        float bo = b_out[r0 + i];
        #pragma unroll
        for (int j = 0; j < 4; j++)
            qsm[(r0+i)*XP + p0 + j] = acc[i][j] + bo;
    }
    __syncthreads();

    // ---- channel LayerNorm per pixel + residual ----
    {
        float ps = 0.f, pq = 0.f;
        for (int i = 0; i < 32; i++) {
            float v = qsm[(cb*32 + i)*XP + p];
            ps += v; pq += v * v;
        }
        colsum[cb][p] = ps; colsq[cb][p] = pq;
    }
    __syncthreads();
    if (t < 32) {
        float s = 0.f, q2 = 0.f;
        #pragma unroll
        for (int sg = 0; sg < 8; sg++) { s += colsum[sg][t]; q2 += colsq[sg][t]; }
        float m   = s * (1.f / 256.f);
        float var = q2 * (1.f / 256.f) - m * m;
        mcol[t] = m;
        rcol[t] = rsqrtf(var + LN_EPS);
    }
    __syncthreads();
    float* ob = out + (size_t)b * CH * NPIX + (size_t)pt * 32;
    #pragma unroll 4
    for (int i = 0; i < 32; i++) {
        int c = cb + i * 8;
        float v = (qsm[c*XP + p] - mcol[p]) * rcol[p] * ln_g[c] + xnsm[c*XP + p];
        ob[(size_t)c * NPIX + p] = v;
    }
}

// ---------------- launch ----------------
extern "C" void kernel_launch(void* const* d_in, const int* in_sizes, int n_in,
                              void* d_out, int out_size) {
    const float* x      = (const float*)d_in[0];
    const float* w_qkv  = (const float*)d_in[1];
    const float* mem_kv = (const float*)d_in[2];
    const float* w_out  = (const float*)d_in[3];
    const float* b_out  = (const float*)d_in[4];
    const float* ln_g   = (const float*)d_in[5];
    float* out = (float*)d_out;

    cudaFuncSetAttribute(k_kv,  cudaFuncAttributeMaxDynamicSharedMemorySize, KV_SMEM_BYTES);
    cudaFuncSetAttribute(k_out, cudaFuncAttributeMaxDynamicSharedMemorySize, OUT_SMEM_BYTES);

    k_zero<<<512, 256>>>();
    k_stats<<<BATCH * CH, 256>>>(x);
    k_kv<<<dim3(NPIX/32, BATCH), 256, KV_SMEM_BYTES>>>(x, w_qkv);
    k_wf<<<dim3(HEADS, BATCH), 256>>>(mem_kv, w_out);
    k_out<<<dim3(NPIX/32, BATCH), 256, OUT_SMEM_BYTES>>>(x, w_qkv, b_out, ln_g, out);
}

// round 6
// speedup vs baseline: 1.3147x; 1.3146x over previous
#include <cuda_runtime.h>
#include <cuda_bf16.h>
#include <math.h>
#include <stdint.h>

#define BATCH 16
#define CH    256
#define NPIX  16384
#define HEADS 8
#define DH    32
#define NMEM  4
#define SCALE_Q 0.5f
#define LN_EPS 1e-5f

// ---------------- helpers ----------------
__device__ __forceinline__ uint32_t smem_u32(const void* p) {
    uint32_t a;
    asm("{ .reg .u64 t; cvta.to.shared.u64 t, %1; cvt.u32.u64 %0, t; }" : "=r"(a) : "l"(p));
    return a;
}
__device__ __forceinline__ void ldsm_x4(uint32_t* r, uint32_t addr) {
    asm volatile("ldmatrix.sync.aligned.m8n8.x4.shared.b16 {%0,%1,%2,%3}, [%4];"
        : "=r"(r[0]), "=r"(r[1]), "=r"(r[2]), "=r"(r[3]) : "r"(addr));
}
__device__ __forceinline__ void ldsm_x2(uint32_t* r, uint32_t addr) {
    asm volatile("ldmatrix.sync.aligned.m8n8.x2.shared.b16 {%0,%1}, [%2];"
        : "=r"(r[0]), "=r"(r[1]) : "r"(addr));
}
__device__ __forceinline__ void mma16816(float* c, const uint32_t* a, const uint32_t* b) {
    asm volatile("mma.sync.aligned.m16n8k16.row.col.f32.bf16.bf16.f32 "
        "{%0,%1,%2,%3}, {%4,%5,%6,%7}, {%8,%9}, {%0,%1,%2,%3};"
        : "+f"(c[0]), "+f"(c[1]), "+f"(c[2]), "+f"(c[3])
        : "r"(a[0]), "r"(a[1]), "r"(a[2]), "r"(a[3]), "r"(b[0]), "r"(b[1]));
}
__device__ __forceinline__ unsigned split_pack(float v) {
    unsigned short h = __bfloat16_as_ushort(__float2bfloat16(v));
    float hf = __bfloat162float(__ushort_as_bfloat16(h));
    unsigned short l = __bfloat16_as_ushort(__float2bfloat16(v - hf));
    return (unsigned)h | ((unsigned)l << 16);
}

// ---------------- scratch ----------------
__device__ float g_mean[BATCH*CH];
__device__ float g_rstd[BATCH*CH];
__device__ float g_S[BATCH*HEADS*DH*DH];
__device__ float g_Z[BATCH*HEADS*DH];
__device__ float g_wf[BATCH*CH*CH];
__device__ unsigned g_whl[768*CH];   // split-packed w_qkv: hi bf16 | lo bf16 << 16

// ---------------- k_zero ----------------
__global__ void k_zero() {
    int i = blockIdx.x * 256 + threadIdx.x;
    if (i < BATCH*HEADS*DH*DH) g_S[i] = 0.f;
    if (i < BATCH*HEADS*DH)    g_Z[i] = 0.f;
}

// ---------------- k_stats ----------------
__global__ __launch_bounds__(256) void k_stats(const float* __restrict__ x) {
    int bc = blockIdx.x;
    const float4* p = (const float4*)(x + (size_t)bc * NPIX);
    float s = 0.f, ss = 0.f;
    for (int i = threadIdx.x; i < NPIX/4; i += 256) {
        float4 v = p[i];
        s  += v.x + v.y + v.z + v.w;
        ss += v.x*v.x + v.y*v.y + v.z*v.z + v.w*v.w;
    }
    __shared__ float rs[256], rq[256];
    rs[threadIdx.x] = s; rq[threadIdx.x] = ss;
    __syncthreads();
    for (int o = 128; o > 0; o >>= 1) {
        if (threadIdx.x < o) { rs[threadIdx.x] += rs[threadIdx.x+o]; rq[threadIdx.x] += rq[threadIdx.x+o]; }
        __syncthreads();
    }
    if (threadIdx.x == 0) {
        float m   = rs[0] * (1.f / NPIX);
        float var = rq[0] * (1.f / NPIX) - m * m;
        g_mean[bc] = m;
        g_rstd[bc] = rsqrtf(var + LN_EPS);
    }
}

// ---------------- k_wprep ----------------
__global__ void k_wprep(const float* __restrict__ w_qkv) {
    int i = blockIdx.x * 256 + threadIdx.x;
    g_whl[i] = split_pack(w_qkv[i]);
}

// ---------------- k_kv_mma: HMMA K/V GEMM + exp + S/Z accumulate ----------------
// CTA: (32-px tile, batch). Rows 0-255 = K, 256-511 = V. K=256 in 4 chunks of 64.
// smem: A_hi[512][72] bf16 @0 (73728B), A_lo @73728, Bt_hi[32][72] @147456, Bt_lo @152064.
// Epilogue alias: eks[256][36] f32 @0, vs[256][36] f32 @36864.
#define SA 72
#define A_HI 0
#define A_LO 73728
#define B_HI 147456
#define B_LO 152064
#define KV_SMEM 156672

__global__ __launch_bounds__(256, 1) void k_kv_mma(const float* __restrict__ x) {
    extern __shared__ char dsm[];
    const int b = blockIdx.y, pt = blockIdx.x;
    const int t = threadIdx.x, lane = t & 31, w = t >> 5;
    const uint32_t smb = smem_u32(dsm);

    const int px0 = pt * 32;
    const float* xb = x + (size_t)b * CH * NPIX + px0;
    const uint4* whl4 = (const uint4*)(g_whl + 256 * CH);   // based at w_qkv row 256 (K start)

    // per-thread ldmatrix address offsets (element units)
    const int lrow = lane & 7, seg = lane >> 3;
    const int aoff = ((seg & 1) * 8 + lrow) * SA + (seg >> 1) * 8;   // A: x4 pattern
    const int l2 = lane & 15;
    const int boff = (l2 & 7) * SA + (l2 >> 3) * 8;                  // B: x2 pattern (row=px)

    float acc[4][4][4];
    #pragma unroll
    for (int m = 0; m < 4; m++)
        #pragma unroll
        for (int n = 0; n < 4; n++)
            #pragma unroll
            for (int q = 0; q < 4; q++) acc[m][n][q] = 0.f;

    for (int c = 0; c < 4; c++) {
        const int cb = c * 64;
        // load A chunk: 512 rows x 64 ch (uint4 = 4 ch), split hi/lo
        #pragma unroll
        for (int i = 0; i < 32; i++) {
            int flat = t + i * 256;          // 0..8191
            int r = flat >> 4, q = flat & 15;
            uint4 u = whl4[(size_t)r * 64 + c * 16 + q];   // base already at row 256
            uint32_t off = (uint32_t)r * (SA*2) + q * 8;
            *(uint2*)(dsm + A_HI + off) = make_uint2(__byte_perm(u.x,u.y,0x5410), __byte_perm(u.z,u.w,0x5410));
            *(uint2*)(dsm + A_LO + off) = make_uint2(__byte_perm(u.x,u.y,0x7632), __byte_perm(u.z,u.w,0x7632));
        }
        // load B chunk: xn [64 ch][32 px] -> Bt[px][ch]
        #pragma unroll
        for (int i = 0; i < 8; i++) {
            int flat = t + i * 256;          // 0..2047
            int ch = flat >> 5, px = flat & 31;
            float m = g_mean[b*CH + cb + ch], r = g_rstd[b*CH + cb + ch];
            float val = (xb[(size_t)(cb + ch) * NPIX + px] - m) * r;
            unsigned pk = split_pack(val);
            uint32_t off = (uint32_t)(px * SA + ch) * 2;
            *(unsigned short*)(dsm + B_HI + off) = (unsigned short)pk;
            *(unsigned short*)(dsm + B_LO + off) = (unsigned short)(pk >> 16);
        }
        __syncthreads();

        #pragma unroll
        for (int ks = 0; ks < 4; ks++) {
            const int k0 = ks * 16;
            uint32_t bh[4][2], bl[4][2];
            #pragma unroll
            for (int n = 0; n < 4; n++) {
                uint32_t bo = (uint32_t)(n * 8 * SA + k0 + boff) * 2;
                ldsm_x2(bh[n], smb + B_HI + bo);
                ldsm_x2(bl[n], smb + B_LO + bo);
            }
            #pragma unroll
            for (int m = 0; m < 4; m++) {
                uint32_t ah[4], al[4];
                uint32_t ao = (uint32_t)((w * 64 + m * 16) * SA + k0 + aoff) * 2;
                ldsm_x4(ah, smb + A_HI + ao);
                ldsm_x4(al, smb + A_LO + ao);
                #pragma unroll
                for (int n = 0; n < 4; n++) {
                    mma16816(acc[m][n], ah, bh[n]);
                    mma16816(acc[m][n], ah, bl[n]);
                    mma16816(acc[m][n], al, bh[n]);
                }
            }
        }
        __syncthreads();
    }

    // ---- epilogue: write exp(K) / V to smem, outer-product accumulate ----
    float* eks = (float*)dsm;              // [256][36]
    float* vs  = (float*)(dsm + 36864);    // [256][36]
    const int gid = lane >> 2, tig = lane & 3;
    #pragma unroll
    for (int m = 0; m < 4; m++) {
        int row = w * 64 + m * 16 + gid;
        #pragma unroll
        for (int n = 0; n < 4; n++) {
            int px = n * 8 + 2 * tig;
            if (w < 4) {   // K rows
                eks[ row      * 36 + px    ] = expf(acc[m][n][0]);
                eks[ row      * 36 + px + 1] = expf(acc[m][n][1]);
                eks[(row + 8) * 36 + px    ] = expf(acc[m][n][2]);
                eks[(row + 8) * 36 + px + 1] = expf(acc[m][n][3]);
            } else {       // V rows
                int vr = row - 256;
                vs[ vr      * 36 + px    ] = acc[m][n][0];
                vs[ vr      * 36 + px + 1] = acc[m][n][1];
                vs[(vr + 8) * 36 + px    ] = acc[m][n][2];
                vs[(vr + 8) * 36 + px + 1] = acc[m][n][3];
            }
        }
    }
    __syncthreads();

    const int h = t >> 5, d = t & 31;
    float sacc[32];
    #pragma unroll
    for (int e = 0; e < 32; e++) sacc[e] = 0.f;
    float z = 0.f;
    const float* krow = eks + (h*32 + d) * 36;
    for (int p4 = 0; p4 < 32; p4 += 4) {
        float4 ek4 = *(const float4*)(krow + p4);
        z += ek4.x + ek4.y + ek4.z + ek4.w;
        #pragma unroll
        for (int e = 0; e < 32; e++) {
            float4 v4 = *(const float4*)(vs + (h*32 + e) * 36 + p4);
            sacc[e] = fmaf(ek4.x, v4.x, fmaf(ek4.y, v4.y,
                      fmaf(ek4.z, v4.z, fmaf(ek4.w, v4.w, sacc[e]))));
        }
    }
    float* Sp = g_S + ((size_t)(b*HEADS + h)*DH + d) * DH;
    #pragma unroll
    for (int e = 0; e < 32; e++) atomicAdd(&Sp[e], sacc[e]);
    atomicAdd(&g_Z[(b*HEADS + h)*DH + d], z);
}

// ---------------- k_wf ----------------
__global__ __launch_bounds__(256) void k_wf(const float* __restrict__ mem_kv,
                                            const float* __restrict__ w_out) {
    __shared__ float ctxsm[DH*DH];
    __shared__ float wsm[CH*33];
    const int h = blockIdx.x, b = blockIdx.y;
    const int t = threadIdx.x;
    {
        int d  = t >> 3;
        int e0 = (t & 7) * 4;
        float ekm[NMEM];
        float zm = 0.f;
        #pragma unroll
        for (int m = 0; m < NMEM; m++) {
            ekm[m] = expf(mem_kv[(h*DH + d)*NMEM + m]);
            zm += ekm[m];
        }
        float inv = 1.f / (g_Z[(b*HEADS + h)*DH + d] + zm);
        #pragma unroll
        for (int j = 0; j < 4; j++) {
            int e = e0 + j;
            float s = g_S[((size_t)(b*HEADS + h)*DH + d)*DH + e];
            float sm = 0.f;
            #pragma unroll
            for (int m = 0; m < NMEM; m++)
                sm = fmaf(ekm[m], mem_kv[HEADS*DH*NMEM + (h*DH + e)*NMEM + m], sm);
            ctxsm[d*DH + e] = (s + sm) * inv;
        }
    }
    #pragma unroll
    for (int i = 0; i < 8; i++) {
        int idx = t + i * 256;
        int c = idx >> 3, eq = (idx & 7) * 4;
        float4 wv = *(const float4*)(w_out + (size_t)c * CH + h*DH + eq);
        wsm[c*33 + eq+0] = wv.x; wsm[c*33 + eq+1] = wv.y;
        wsm[c*33 + eq+2] = wv.z; wsm[c*33 + eq+3] = wv.w;
    }
    __syncthreads();
    float acc[DH];
    #pragma unroll
    for (int d = 0; d < DH; d++) acc[d] = 0.f;
    for (int e = 0; e < DH; e++) {
        float wv = wsm[t*33 + e];
        #pragma unroll
        for (int d = 0; d < DH; d++)
            acc[d] = fmaf(wv, ctxsm[d*DH + e], acc[d]);
    }
    float* dst = g_wf + ((size_t)b*CH + t)*CH + h*DH;
    #pragma unroll
    for (int d = 0; d < DH; d++) dst[d] = acc[d];
}

// ---------------- k_out: q GEMM -> softmax -> Wf GEMM -> LN -> residual ----------------
#define XP 36
#define OUT_SMEM_BYTES ((9216 + 9216 + 2080) * 4)

__global__ __launch_bounds__(256, 2) void k_out(const float* __restrict__ x,
                                                const float* __restrict__ w_qkv,
                                                const float* __restrict__ b_out,
                                                const float* __restrict__ ln_g,
                                                float* __restrict__ out) {
    extern __shared__ float sm[];
    float* xnsm = sm;
    float* qsm  = xnsm + CH*XP;
    float* wsm  = qsm  + CH*XP;
    __shared__ float colsum[8][32], colsq[8][32], mcol[32], rcol[32];

    const int b = blockIdx.y, pt = blockIdx.x;
    const int t = threadIdx.x;
    const int p = t & 31, cb = t >> 5;
    const float* xb = x + (size_t)b * CH * NPIX + (size_t)pt * 32;

    #pragma unroll 4
    for (int i = 0; i < 32; i++) {
        int c = cb + i * 8;
        float xv = xb[(size_t)c * NPIX + p];
        xnsm[c*XP + p] = (xv - g_mean[b*CH + c]) * g_rstd[b*CH + c];
    }
    const int r0 = (t >> 3) * 8;
    const int p0 = (t & 7) * 4;
    float acc[8][4];
    #pragma unroll
    for (int i = 0; i < 8; i++)
        #pragma unroll
        for (int j = 0; j < 4; j++) acc[i][j] = 0.f;

    for (int c0 = 0; c0 < CH; c0 += 8) {
        __syncthreads();
        #pragma unroll
        for (int i = 0; i < 2; i++) {
            int idx = t + i * 256;
            int r = idx >> 1, cq = (idx & 1) * 4;
            float4 wv = *(const float4*)(w_qkv + (size_t)r * CH + c0 + cq);
            wsm[(cq+0)*260 + r] = wv.x; wsm[(cq+1)*260 + r] = wv.y;
            wsm[(cq+2)*260 + r] = wv.z; wsm[(cq+3)*260 + r] = wv.w;
        }
        __syncthreads();
        #pragma unroll
        for (int k = 0; k < 8; k++) {
            float wf[8], xf[4];
            *(float4*)&wf[0] = *(const float4*)&wsm[k*260 + r0];
            *(float4*)&wf[4] = *(const float4*)&wsm[k*260 + r0 + 4];
            *(float4*)&xf[0] = *(const float4*)&xnsm[(c0+k)*XP + p0];
            #pragma unroll
            for (int i = 0; i < 8; i++)
                #pragma unroll
                for (int j = 0; j < 4; j++)
                    acc[i][j] = fmaf(wf[i], xf[j], acc[i][j]);
        }
    }
    __syncthreads();
    #pragma unroll
    for (int i = 0; i < 8; i++)
        #pragma unroll
        for (int j = 0; j < 4; j++)
            qsm[(r0+i)*XP + p0 + j] = acc[i][j];
    __syncthreads();
    {
        float* qc = qsm + (size_t)(cb * 32) * XP + p;
        float vals[32];
        float mx = -1e30f;
        #pragma unroll
        for (int dd = 0; dd < 32; dd++) { vals[dd] = qc[dd*XP]; mx = fmaxf(mx, vals[dd]); }
        float s = 0.f;
        #pragma unroll
        for (int dd = 0; dd < 32; dd++) { vals[dd] = expf(vals[dd] - mx); s += vals[dd]; }
        float inv = SCALE_Q / s;
        #pragma unroll
        for (int dd = 0; dd < 32; dd++) qc[dd*XP] = vals[dd] * inv;
    }
    __syncthreads();
    #pragma unroll
    for (int i = 0; i < 8; i++)
        #pragma unroll
        for (int j = 0; j < 4; j++) acc[i][j] = 0.f;
    const float* wf_b = g_wf + (size_t)b * CH * CH;
    for (int c0 = 0; c0 < CH; c0 += 8) {
        __syncthreads();
        #pragma unroll
        for (int i = 0; i < 2; i++) {
            int idx = t + i * 256;
            int r = idx >> 1, cq = (idx & 1) * 4;
            float4 wv = *(const float4*)(wf_b + (size_t)r * CH + c0 + cq);
            wsm[(cq+0)*260 + r] = wv.x; wsm[(cq+1)*260 + r] = wv.y;
            wsm[(cq+2)*260 + r] = wv.z; wsm[(cq+3)*260 + r] = wv.w;
        }
        __syncthreads();
        #pragma unroll
        for (int k = 0; k < 8; k++) {
            float wf[8], xf[4];
            *(float4*)&wf[0] = *(const float4*)&wsm[k*260 + r0];
            *(float4*)&wf[4] = *(const float4*)&wsm[k*260 + r0 + 4];
            *(float4*)&xf[0] = *(const float4*)&qsm[(c0+k)*XP + p0];
            #pragma unroll
            for (int i = 0; i < 8; i++)
                #pragma unroll
                for (int j = 0; j < 4; j++)
                    acc[i][j] = fmaf(wf[i], xf[j], acc[i][j]);
        }
    }
    __syncthreads();
    #pragma unroll
    for (int i = 0; i < 8; i++) {
        float bo = b_out[r0 + i];
        #pragma unroll
        for (int j = 0; j < 4; j++)
            qsm[(r0+i)*XP + p0 + j] = acc[i][j] + bo;
    }
    __syncthreads();
    {
        float ps = 0.f, pq = 0.f;
        for (int i = 0; i < 32; i++) {
            float v = qsm[(cb*32 + i)*XP + p];
            ps += v; pq += v * v;
        }
        colsum[cb][p] = ps; colsq[cb][p] = pq;
    }
    __syncthreads();
    if (t < 32) {
        float s = 0.f, q2 = 0.f;
        #pragma unroll
        for (int sg = 0; sg < 8; sg++) { s += colsum[sg][t]; q2 += colsq[sg][t]; }
        float m   = s * (1.f / 256.f);
        float var = q2 * (1.f / 256.f) - m * m;
        mcol[t] = m;
        rcol[t] = rsqrtf(var + LN_EPS);
    }
    __syncthreads();
    float* ob = out + (size_t)b * CH * NPIX + (size_t)pt * 32;
    #pragma unroll 4
    for (int i = 0; i < 32; i++) {
        int c = cb + i * 8;
        float v = (qsm[c*XP + p] - mcol[p]) * rcol[p] * ln_g[c] + xnsm[c*XP + p];
        ob[(size_t)c * NPIX + p] = v;
    }
}

// ---------------- launch ----------------
extern "C" void kernel_launch(void* const* d_in, const int* in_sizes, int n_in,
                              void* d_out, int out_size) {
    const float* x      = (const float*)d_in[0];
    const float* w_qkv  = (const float*)d_in[1];
    const float* mem_kv = (const float*)d_in[2];
    const float* w_out  = (const float*)d_in[3];
    const float* b_out  = (const float*)d_in[4];
    const float* ln_g   = (const float*)d_in[5];
    float* out = (float*)d_out;

    cudaFuncSetAttribute(k_kv_mma, cudaFuncAttributeMaxDynamicSharedMemorySize, KV_SMEM);
    cudaFuncSetAttribute(k_out,    cudaFuncAttributeMaxDynamicSharedMemorySize, OUT_SMEM_BYTES);

    k_zero<<<512, 256>>>();
    k_stats<<<BATCH * CH, 256>>>(x);
    k_wprep<<<768, 256>>>(w_qkv);
    k_kv_mma<<<dim3(NPIX/32, BATCH), 256, KV_SMEM>>>(x);
    k_wf<<<dim3(HEADS, BATCH), 256>>>(mem_kv, w_out);
    k_out<<<dim3(NPIX/32, BATCH), 256, OUT_SMEM_BYTES>>>(x, w_qkv, b_out, ln_g, out);
}

// round 8
// speedup vs baseline: 1.6041x; 1.2201x over previous
#include <cuda_runtime.h>
#include <cuda_bf16.h>
#include <math.h>
#include <stdint.h>

#define BATCH 16
#define CH    256
#define NPIX  16384
#define HEADS 8
#define DH    32
#define NMEM  4
#define SCALE_Q 0.5f
#define LN_EPS 1e-5f

// ---------------- helpers ----------------
__device__ __forceinline__ uint32_t smem_u32(const void* p) {
    uint32_t a;
    asm("{ .reg .u64 t; cvta.to.shared.u64 t, %1; cvt.u32.u64 %0, t; }" : "=r"(a) : "l"(p));
    return a;
}
__device__ __forceinline__ void ldsm_x4(uint32_t* r, uint32_t addr) {
    asm volatile("ldmatrix.sync.aligned.m8n8.x4.shared.b16 {%0,%1,%2,%3}, [%4];"
        : "=r"(r[0]), "=r"(r[1]), "=r"(r[2]), "=r"(r[3]) : "r"(addr));
}
__device__ __forceinline__ void ldsm_x2(uint32_t* r, uint32_t addr) {
    asm volatile("ldmatrix.sync.aligned.m8n8.x2.shared.b16 {%0,%1}, [%2];"
        : "=r"(r[0]), "=r"(r[1]) : "r"(addr));
}
__device__ __forceinline__ void mma16816(float* c, const uint32_t* a, const uint32_t* b) {
    asm volatile("mma.sync.aligned.m16n8k16.row.col.f32.bf16.bf16.f32 "
        "{%0,%1,%2,%3}, {%4,%5,%6,%7}, {%8,%9}, {%0,%1,%2,%3};"
        : "+f"(c[0]), "+f"(c[1]), "+f"(c[2]), "+f"(c[3])
        : "r"(a[0]), "r"(a[1]), "r"(a[2]), "r"(a[3]), "r"(b[0]), "r"(b[1]));
}
__device__ __forceinline__ unsigned split_pack(float v) {
    unsigned short h = __bfloat16_as_ushort(__float2bfloat16(v));
    float hf = __bfloat162float(__ushort_as_bfloat16(h));
    unsigned short l = __bfloat16_as_ushort(__float2bfloat16(v - hf));
    return (unsigned)h | ((unsigned)l << 16);
}

// ---------------- scratch ----------------
__device__ float g_mean[BATCH*CH];
__device__ float g_rstd[BATCH*CH];
__device__ float g_S[BATCH*HEADS*DH*DH];
__device__ float g_Z[BATCH*HEADS*DH];
__device__ unsigned g_whl[768*CH];             // split-packed w_qkv
__device__ unsigned g_wfhl[BATCH*CH*CH];       // split-packed fused Wf (per batch)

// ---------------- k_zero ----------------
__global__ void k_zero() {
    int i = blockIdx.x * 256 + threadIdx.x;
    if (i < BATCH*HEADS*DH*DH) g_S[i] = 0.f;
    if (i < BATCH*HEADS*DH)    g_Z[i] = 0.f;
}

// ---------------- k_stats ----------------
__global__ __launch_bounds__(256) void k_stats(const float* __restrict__ x) {
    int bc = blockIdx.x;
    const float4* p = (const float4*)(x + (size_t)bc * NPIX);
    float s = 0.f, ss = 0.f;
    for (int i = threadIdx.x; i < NPIX/4; i += 256) {
        float4 v = p[i];
        s  += v.x + v.y + v.z + v.w;
        ss += v.x*v.x + v.y*v.y + v.z*v.z + v.w*v.w;
    }
    __shared__ float rs[256], rq[256];
    rs[threadIdx.x] = s; rq[threadIdx.x] = ss;
    __syncthreads();
    for (int o = 128; o > 0; o >>= 1) {
        if (threadIdx.x < o) { rs[threadIdx.x] += rs[threadIdx.x+o]; rq[threadIdx.x] += rq[threadIdx.x+o]; }
        __syncthreads();
    }
    if (threadIdx.x == 0) {
        float m   = rs[0] * (1.f / NPIX);
        float var = rq[0] * (1.f / NPIX) - m * m;
        g_mean[bc] = m;
        g_rstd[bc] = rsqrtf(var + LN_EPS);
    }
}

// ---------------- k_wprep ----------------
__global__ void k_wprep(const float* __restrict__ w_qkv) {
    int i = blockIdx.x * 256 + threadIdx.x;
    g_whl[i] = split_pack(w_qkv[i]);
}

// ---------------- k_kv_mma: HMMA K/V GEMM + exp + S/Z accumulate (unchanged) ------
#define SA 72
#define A_HI 0
#define A_LO 73728
#define B_HI 147456
#define B_LO 152064
#define KV_SMEM 156672

__global__ __launch_bounds__(256, 1) void k_kv_mma(const float* __restrict__ x) {
    extern __shared__ char dsm[];
    const int b = blockIdx.y, pt = blockIdx.x;
    const int t = threadIdx.x, lane = t & 31, w = t >> 5;
    const uint32_t smb = smem_u32(dsm);

    const int px0 = pt * 32;
    const float* xb = x + (size_t)b * CH * NPIX + px0;
    const uint4* whl4 = (const uint4*)(g_whl + 256 * CH);

    const int lrow = lane & 7, seg = lane >> 3;
    const int aoff = ((seg & 1) * 8 + lrow) * SA + (seg >> 1) * 8;
    const int l2 = lane & 15;
    const int boff = (l2 & 7) * SA + (l2 >> 3) * 8;

    float acc[4][4][4];
    #pragma unroll
    for (int m = 0; m < 4; m++)
        #pragma unroll
        for (int n = 0; n < 4; n++)
            #pragma unroll
            for (int q = 0; q < 4; q++) acc[m][n][q] = 0.f;

    for (int c = 0; c < 4; c++) {
        const int cb = c * 64;
        #pragma unroll
        for (int i = 0; i < 32; i++) {
            int flat = t + i * 256;
            int r = flat >> 4, q = flat & 15;
            uint4 u = whl4[(size_t)r * 64 + c * 16 + q];
            uint32_t off = (uint32_t)r * (SA*2) + q * 8;
            *(uint2*)(dsm + A_HI + off) = make_uint2(__byte_perm(u.x,u.y,0x5410), __byte_perm(u.z,u.w,0x5410));
            *(uint2*)(dsm + A_LO + off) = make_uint2(__byte_perm(u.x,u.y,0x7632), __byte_perm(u.z,u.w,0x7632));
        }
        #pragma unroll
        for (int i = 0; i < 8; i++) {
            int flat = t + i * 256;
            int ch = flat >> 5, px = flat & 31;
            float m = g_mean[b*CH + cb + ch], r = g_rstd[b*CH + cb + ch];
            float val = (xb[(size_t)(cb + ch) * NPIX + px] - m) * r;
            unsigned pk = split_pack(val);
            uint32_t off = (uint32_t)(px * SA + ch) * 2;
            *(unsigned short*)(dsm + B_HI + off) = (unsigned short)pk;
            *(unsigned short*)(dsm + B_LO + off) = (unsigned short)(pk >> 16);
        }
        __syncthreads();

        #pragma unroll
        for (int ks = 0; ks < 4; ks++) {
            const int k0 = ks * 16;
            uint32_t bh[4][2], bl[4][2];
            #pragma unroll
            for (int n = 0; n < 4; n++) {
                uint32_t bo = (uint32_t)(n * 8 * SA + k0 + boff) * 2;
                ldsm_x2(bh[n], smb + B_HI + bo);
                ldsm_x2(bl[n], smb + B_LO + bo);
            }
            #pragma unroll
            for (int m = 0; m < 4; m++) {
                uint32_t ah[4], al[4];
                uint32_t ao = (uint32_t)((w * 64 + m * 16) * SA + k0 + aoff) * 2;
                ldsm_x4(ah, smb + A_HI + ao);
                ldsm_x4(al, smb + A_LO + ao);
                #pragma unroll
                for (int n = 0; n < 4; n++) {
                    mma16816(acc[m][n], ah, bh[n]);
                    mma16816(acc[m][n], ah, bl[n]);
                    mma16816(acc[m][n], al, bh[n]);
                }
            }
        }
        __syncthreads();
    }

    float* eks = (float*)dsm;
    float* vs  = (float*)(dsm + 36864);
    const int gid = lane >> 2, tig = lane & 3;
    #pragma unroll
    for (int m = 0; m < 4; m++) {
        int row = w * 64 + m * 16 + gid;
        #pragma unroll
        for (int n = 0; n < 4; n++) {
            int px = n * 8 + 2 * tig;
            if (w < 4) {
                eks[ row      * 36 + px    ] = expf(acc[m][n][0]);
                eks[ row      * 36 + px + 1] = expf(acc[m][n][1]);
                eks[(row + 8) * 36 + px    ] = expf(acc[m][n][2]);
                eks[(row + 8) * 36 + px + 1] = expf(acc[m][n][3]);
            } else {
                int vr = row - 256;
                vs[ vr      * 36 + px    ] = acc[m][n][0];
                vs[ vr      * 36 + px + 1] = acc[m][n][1];
                vs[(vr + 8) * 36 + px    ] = acc[m][n][2];
                vs[(vr + 8) * 36 + px + 1] = acc[m][n][3];
            }
        }
    }
    __syncthreads();

    const int h = t >> 5, d = t & 31;
    float sacc[32];
    #pragma unroll
    for (int e = 0; e < 32; e++) sacc[e] = 0.f;
    float z = 0.f;
    const float* krow = eks + (h*32 + d) * 36;
    for (int p4 = 0; p4 < 32; p4 += 4) {
        float4 ek4 = *(const float4*)(krow + p4);
        z += ek4.x + ek4.y + ek4.z + ek4.w;
        #pragma unroll
        for (int e = 0; e < 32; e++) {
            float4 v4 = *(const float4*)(vs + (h*32 + e) * 36 + p4);
            sacc[e] = fmaf(ek4.x, v4.x, fmaf(ek4.y, v4.y,
                      fmaf(ek4.z, v4.z, fmaf(ek4.w, v4.w, sacc[e]))));
        }
    }
    float* Sp = g_S + ((size_t)(b*HEADS + h)*DH + d) * DH;
    #pragma unroll
    for (int e = 0; e < 32; e++) atomicAdd(&Sp[e], sacc[e]);
    atomicAdd(&g_Z[(b*HEADS + h)*DH + d], z);
}

// ---------------- k_wf: finalize ctx, fold into W_out, write split-packed -----------
__global__ __launch_bounds__(256) void k_wf(const float* __restrict__ mem_kv,
                                            const float* __restrict__ w_out) {
    __shared__ float ctxsm[DH*DH];
    __shared__ float wsm[CH*33];
    const int h = blockIdx.x, b = blockIdx.y;
    const int t = threadIdx.x;
    {
        int d  = t >> 3;
        int e0 = (t & 7) * 4;
        float ekm[NMEM];
        float zm = 0.f;
        #pragma unroll
        for (int m = 0; m < NMEM; m++) {
            ekm[m] = expf(mem_kv[(h*DH + d)*NMEM + m]);
            zm += ekm[m];
        }
        float inv = 1.f / (g_Z[(b*HEADS + h)*DH + d] + zm);
        #pragma unroll
        for (int j = 0; j < 4; j++) {
            int e = e0 + j;
            float s = g_S[((size_t)(b*HEADS + h)*DH + d)*DH + e];
            float sm = 0.f;
            #pragma unroll
            for (int m = 0; m < NMEM; m++)
                sm = fmaf(ekm[m], mem_kv[HEADS*DH*NMEM + (h*DH + e)*NMEM + m], sm);
            ctxsm[d*DH + e] = (s + sm) * inv;
        }
    }
    #pragma unroll
    for (int i = 0; i < 8; i++) {
        int idx = t + i * 256;
        int c = idx >> 3, eq = (idx & 7) * 4;
        float4 wv = *(const float4*)(w_out + (size_t)c * CH + h*DH + eq);
        wsm[c*33 + eq+0] = wv.x; wsm[c*33 + eq+1] = wv.y;
        wsm[c*33 + eq+2] = wv.z; wsm[c*33 + eq+3] = wv.w;
    }
    __syncthreads();
    float acc[DH];
    #pragma unroll
    for (int d = 0; d < DH; d++) acc[d] = 0.f;
    for (int e = 0; e < DH; e++) {
        float wv = wsm[t*33 + e];
        #pragma unroll
        for (int d = 0; d < DH; d++)
            acc[d] = fmaf(wv, ctxsm[d*DH + e], acc[d]);
    }
    unsigned* dst = g_wfhl + ((size_t)b*CH + t)*CH + h*DH;
    #pragma unroll
    for (int d = 0; d < DH; d++) dst[d] = split_pack(acc[d]);
}

// ---------------- k_out_mma: HMMA q GEMM -> softmax -> HMMA Wf GEMM -> LN -> res ----
// smem: X (xn f32 [256][36]) @0, A_hi @36864, A_lo @73728 ([256][72] bf16),
//       B_hi @110592, B_lo @115200 ([32][72] bf16), Q (f32 [256][36]) @119808.
#define OX    0
#define OA_HI 36864
#define OA_LO 73728
#define OB_HI 110592
#define OB_LO 115200
#define OQ    119808
#define OUT_SMEM 156672

__global__ __launch_bounds__(256, 1) void k_out_mma(const float* __restrict__ x,
                                                    const float* __restrict__ b_out,
                                                    const float* __restrict__ ln_g,
                                                    float* __restrict__ out) {
    extern __shared__ char dsm[];
    __shared__ float colsum[8][32], colsq[8][32], mcol[32], rcol[32];
    const int b = blockIdx.y, pt = blockIdx.x;
    const int t = threadIdx.x, lane = t & 31, w = t >> 5;
    const uint32_t smb = smem_u32(dsm);
    float* X = (float*)(dsm + OX);
    float* Q = (float*)(dsm + OQ);

    const int p = t & 31, cb = t >> 5;
    const float* xb = x + (size_t)b * CH * NPIX + (size_t)pt * 32;

    // stage xn fp32 (GEMM1 source + residual)
    #pragma unroll 4
    for (int i = 0; i < 32; i++) {
        int c = cb + i * 8;
        float xv = xb[(size_t)c * NPIX + p];
        X[c*36 + p] = (xv - g_mean[b*CH + c]) * g_rstd[b*CH + c];
    }
    __syncthreads();

    const int lrow = lane & 7, seg = lane >> 3;
    const int aoff = ((seg & 1) * 8 + lrow) * SA + (seg >> 1) * 8;
    const int l2 = lane & 15;
    const int boff = (l2 & 7) * SA + (l2 >> 3) * 8;
    const int gid = lane >> 2, tig = lane & 3;

    const uint4* wq4 = (const uint4*)g_whl;                              // Q weights rows 0..255
    const uint4* wf4 = (const uint4*)(g_wfhl + (size_t)b * CH * CH);     // fused Wf rows

    float acc[2][4][4];

    // ================= two GEMM passes =================
    #pragma unroll 1
    for (int pass = 0; pass < 2; pass++) {
        const uint4* wsrc = pass ? wf4 : wq4;
        #pragma unroll
        for (int m = 0; m < 2; m++)
            #pragma unroll
            for (int n = 0; n < 4; n++)
                #pragma unroll
                for (int q = 0; q < 4; q++) acc[m][n][q] = 0.f;

        #pragma unroll 1
        for (int c = 0; c < 4; c++) {
            // pack A chunk: 256 rows x 64 ch
            #pragma unroll
            for (int i = 0; i < 16; i++) {
                int flat = t + i * 256;
                int r = flat >> 4, q = flat & 15;
                uint4 u = wsrc[(size_t)r * 64 + c * 16 + q];
                uint32_t off = (uint32_t)r * (SA*2) + q * 8;
                *(uint2*)(dsm + OA_HI + off) = make_uint2(__byte_perm(u.x,u.y,0x5410), __byte_perm(u.z,u.w,0x5410));
                *(uint2*)(dsm + OA_LO + off) = make_uint2(__byte_perm(u.x,u.y,0x7632), __byte_perm(u.z,u.w,0x7632));
            }
            // pack B chunk from smem source (X for pass 0, Q for pass 1)
            const float* src = pass ? Q : X;
            #pragma unroll
            for (int i = 0; i < 8; i++) {
                int flat = t + i * 256;
                int ch = flat >> 5, px = flat & 31;
                unsigned pk = split_pack(src[(c*64 + ch)*36 + px]);
                uint32_t off = (uint32_t)(px * SA + ch) * 2;
                *(unsigned short*)(dsm + OB_HI + off) = (unsigned short)pk;
                *(unsigned short*)(dsm + OB_LO + off) = (unsigned short)(pk >> 16);
            }
            __syncthreads();

            #pragma unroll
            for (int ks = 0; ks < 4; ks++) {
                const int k0 = ks * 16;
                uint32_t bh[4][2], bl[4][2];
                #pragma unroll
                for (int n = 0; n < 4; n++) {
                    uint32_t bo = (uint32_t)(n * 8 * SA + k0 + boff) * 2;
                    ldsm_x2(bh[n], smb + OB_HI + bo);
                    ldsm_x2(bl[n], smb + OB_LO + bo);
                }
                #pragma unroll
                for (int m = 0; m < 2; m++) {
                    uint32_t ah[4], al[4];
                    uint32_t ao = (uint32_t)((w * 32 + m * 16) * SA + k0 + aoff) * 2;
                    ldsm_x4(ah, smb + OA_HI + ao);
                    ldsm_x4(al, smb + OA_LO + ao);
                    #pragma unroll
                    for (int n = 0; n < 4; n++) {
                        mma16816(acc[m][n], ah, bh[n]);
                        mma16816(acc[m][n], ah, bl[n]);
                        mma16816(acc[m][n], al, bh[n]);
                    }
                }
            }
            __syncthreads();
        }

        if (pass == 0) {
            // store q -> Q, then per-(head,pixel) softmax
            #pragma unroll
            for (int m = 0; m < 2; m++) {
                int row = w * 32 + m * 16 + gid;
                #pragma unroll
                for (int n = 0; n < 4; n++) {
                    int px = n * 8 + 2 * tig;
                    Q[ row      * 36 + px    ] = acc[m][n][0];
                    Q[ row      * 36 + px + 1] = acc[m][n][1];
                    Q[(row + 8) * 36 + px    ] = acc[m][n][2];
                    Q[(row + 8) * 36 + px + 1] = acc[m][n][3];
                }
            }
            __syncthreads();
            {
                float* qc = Q + (size_t)(cb * 32) * 36 + p;
                float vals[32];
                float mx = -1e30f;
                #pragma unroll
                for (int dd = 0; dd < 32; dd++) { vals[dd] = qc[dd*36]; mx = fmaxf(mx, vals[dd]); }
                float s = 0.f;
                #pragma unroll
                for (int dd = 0; dd < 32; dd++) { vals[dd] = expf(vals[dd] - mx); s += vals[dd]; }
                float inv = SCALE_Q / s;
                #pragma unroll
                for (int dd = 0; dd < 32; dd++) qc[dd*36] = vals[dd] * inv;
            }
            __syncthreads();
        }
    }

    // ---- bias + store y -> Q ----
    #pragma unroll
    for (int m = 0; m < 2; m++) {
        int row = w * 32 + m * 16 + gid;
        float bo0 = b_out[row], bo8 = b_out[row + 8];
        #pragma unroll
        for (int n = 0; n < 4; n++) {
            int px = n * 8 + 2 * tig;
            Q[ row      * 36 + px    ] = acc[m][n][0] + bo0;
            Q[ row      * 36 + px + 1] = acc[m][n][1] + bo0;
            Q[(row + 8) * 36 + px    ] = acc[m][n][2] + bo8;
            Q[(row + 8) * 36 + px + 1] = acc[m][n][3] + bo8;
        }
    }
    __syncthreads();

    // ---- channel LayerNorm + residual ----
    {
        float ps = 0.f, pq = 0.f;
        for (int i = 0; i < 32; i++) {
            float v = Q[(cb*32 + i)*36 + p];
            ps += v; pq += v * v;
        }
        colsum[cb][p] = ps; colsq[cb][p] = pq;
    }
    __syncthreads();
    if (t < 32) {
        float s = 0.f, q2 = 0.f;
        #pragma unroll
        for (int sg = 0; sg < 8; sg++) { s += colsum[sg][t]; q2 += colsq[sg][t]; }
        float m   = s * (1.f / 256.f);
        float var = q2 * (1.f / 256.f) - m * m;
        mcol[t] = m;
        rcol[t] = rsqrtf(var + LN_EPS);
    }
    __syncthreads();
    float* ob = out + (size_t)b * CH * NPIX + (size_t)pt * 32;
    #pragma unroll 4
    for (int i = 0; i < 32; i++) {
        int c = cb + i * 8;
        float v = (Q[c*36 + p] - mcol[p]) * rcol[p] * ln_g[c] + X[c*36 + p];
        ob[(size_t)c * NPIX + p] = v;
    }
}

// ---------------- launch ----------------
extern "C" void kernel_launch(void* const* d_in, const int* in_sizes, int n_in,
                              void* d_out, int out_size) {
    const float* x      = (const float*)d_in[0];
    const float* w_qkv  = (const float*)d_in[1];
    const float* mem_kv = (const float*)d_in[2];
    const float* w_out  = (const float*)d_in[3];
    const float* b_out  = (const float*)d_in[4];
    const float* ln_g   = (const float*)d_in[5];
    float* out = (float*)d_out;

    cudaFuncSetAttribute(k_kv_mma,  cudaFuncAttributeMaxDynamicSharedMemorySize, KV_SMEM);
    cudaFuncSetAttribute(k_out_mma, cudaFuncAttributeMaxDynamicSharedMemorySize, OUT_SMEM);

    k_zero<<<512, 256>>>();
    k_stats<<<BATCH * CH, 256>>>(x);
    k_wprep<<<768, 256>>>(w_qkv);
    k_kv_mma<<<dim3(NPIX/32, BATCH), 256, KV_SMEM>>>(x);
    k_wf<<<dim3(HEADS, BATCH), 256>>>(mem_kv, w_out);
    k_out_mma<<<dim3(NPIX/32, BATCH), 256, OUT_SMEM>>>(x, b_out, ln_g, out);
}

// round 10
// speedup vs baseline: 1.8136x; 1.1307x over previous
#include <cuda_runtime.h>
#include <cuda_bf16.h>
#include <math.h>
#include <stdint.h>

#define BATCH 16
#define CH    256
#define NPIX  16384
#define HEADS 8
#define DH    32
#define NMEM  4
#define SCALE_Q 0.5f
#define LN_EPS 1e-5f

// ---------------- helpers ----------------
__device__ __forceinline__ uint32_t smem_u32(const void* p) {
    uint32_t a;
    asm("{ .reg .u64 t; cvta.to.shared.u64 t, %1; cvt.u32.u64 %0, t; }" : "=r"(a) : "l"(p));
    return a;
}
__device__ __forceinline__ void ldsm_x4(uint32_t* r, uint32_t addr) {
    asm volatile("ldmatrix.sync.aligned.m8n8.x4.shared.b16 {%0,%1,%2,%3}, [%4];"
        : "=r"(r[0]), "=r"(r[1]), "=r"(r[2]), "=r"(r[3]) : "r"(addr));
}
__device__ __forceinline__ void ldsm_x2(uint32_t* r, uint32_t addr) {
    asm volatile("ldmatrix.sync.aligned.m8n8.x2.shared.b16 {%0,%1}, [%2];"
        : "=r"(r[0]), "=r"(r[1]) : "r"(addr));
}
__device__ __forceinline__ void mma16816(float* c, const uint32_t* a, const uint32_t* b) {
    asm volatile("mma.sync.aligned.m16n8k16.row.col.f32.bf16.bf16.f32 "
        "{%0,%1,%2,%3}, {%4,%5,%6,%7}, {%8,%9}, {%0,%1,%2,%3};"
        : "+f"(c[0]), "+f"(c[1]), "+f"(c[2]), "+f"(c[3])
        : "r"(a[0]), "r"(a[1]), "r"(a[2]), "r"(a[3]), "r"(b[0]), "r"(b[1]));
}
__device__ __forceinline__ unsigned split_pack(float v) {
    unsigned short h = __bfloat16_as_ushort(__float2bfloat16(v));
    float hf = __bfloat162float(__ushort_as_bfloat16(h));
    unsigned short l = __bfloat16_as_ushort(__float2bfloat16(v - hf));
    return (unsigned)h | ((unsigned)l << 16);
}

// ---------------- scratch ----------------
__device__ float g_mean[BATCH*CH];
__device__ float g_rstd[BATCH*CH];
__device__ float g_S[BATCH*HEADS*DH*DH];
__device__ float g_Z[BATCH*HEADS*DH];
__device__ unsigned g_whl[768*CH];             // split-packed w_qkv
__device__ unsigned g_wfhl[BATCH*CH*CH];       // split-packed fused Wf (per batch)

// ---------------- k_zero ----------------
__global__ void k_zero() {
    int i = blockIdx.x * 256 + threadIdx.x;
    if (i < BATCH*HEADS*DH*DH) g_S[i] = 0.f;
    if (i < BATCH*HEADS*DH)    g_Z[i] = 0.f;
}

// ---------------- k_stats ----------------
__global__ __launch_bounds__(256) void k_stats(const float* __restrict__ x) {
    int bc = blockIdx.x;
    const float4* p = (const float4*)(x + (size_t)bc * NPIX);
    float s = 0.f, ss = 0.f;
    for (int i = threadIdx.x; i < NPIX/4; i += 256) {
        float4 v = p[i];
        s  += v.x + v.y + v.z + v.w;
        ss += v.x*v.x + v.y*v.y + v.z*v.z + v.w*v.w;
    }
    __shared__ float rs[256], rq[256];
    rs[threadIdx.x] = s; rq[threadIdx.x] = ss;
    __syncthreads();
    for (int o = 128; o > 0; o >>= 1) {
        if (threadIdx.x < o) { rs[threadIdx.x] += rs[threadIdx.x+o]; rq[threadIdx.x] += rq[threadIdx.x+o]; }
        __syncthreads();
    }
    if (threadIdx.x == 0) {
        float m   = rs[0] * (1.f / NPIX);
        float var = rq[0] * (1.f / NPIX) - m * m;
        g_mean[bc] = m;
        g_rstd[bc] = rsqrtf(var + LN_EPS);
    }
}

// ---------------- k_wprep ----------------
__global__ void k_wprep(const float* __restrict__ w_qkv) {
    int i = blockIdx.x * 256 + threadIdx.x;
    g_whl[i] = split_pack(w_qkv[i]);
}

// ---------------- k_kv_mma: HMMA K/V GEMM + MMA epilogue for S ----------------
#define SA 72
#define A_HI 0
#define A_LO 73728
#define B_HI 147456
#define B_LO 152064
#define KV_SMEM 156672
// epilogue alias (bf16 split, stride 40 elems = 80B rows)
#define SV 40
#define EK_HI 0
#define EK_LO 20480
#define V_HI  40960
#define V_LO  61440

__global__ __launch_bounds__(256, 1) void k_kv_mma(const float* __restrict__ x) {
    extern __shared__ char dsm[];
    const int b = blockIdx.y, pt = blockIdx.x;
    const int t = threadIdx.x, lane = t & 31, w = t >> 5;
    const uint32_t smb = smem_u32(dsm);

    const int px0 = pt * 32;
    const float* xb = x + (size_t)b * CH * NPIX + px0;
    const uint4* whl4 = (const uint4*)(g_whl + 256 * CH);

    const int lrow = lane & 7, seg = lane >> 3;
    const int aoff = ((seg & 1) * 8 + lrow) * SA + (seg >> 1) * 8;
    const int l2 = lane & 15;
    const int boff = (l2 & 7) * SA + (l2 >> 3) * 8;
    const int gid = lane >> 2, tig = lane & 3;

    float acc[4][4][4];
    #pragma unroll
    for (int m = 0; m < 4; m++)
        #pragma unroll
        for (int n = 0; n < 4; n++)
            #pragma unroll
            for (int q = 0; q < 4; q++) acc[m][n][q] = 0.f;

    for (int c = 0; c < 4; c++) {
        const int cb = c * 64;
        #pragma unroll
        for (int i = 0; i < 32; i++) {
            int flat = t + i * 256;
            int r = flat >> 4, q = flat & 15;
            uint4 u = whl4[(size_t)r * 64 + c * 16 + q];
            uint32_t off = (uint32_t)r * (SA*2) + q * 8;
            *(uint2*)(dsm + A_HI + off) = make_uint2(__byte_perm(u.x,u.y,0x5410), __byte_perm(u.z,u.w,0x5410));
            *(uint2*)(dsm + A_LO + off) = make_uint2(__byte_perm(u.x,u.y,0x7632), __byte_perm(u.z,u.w,0x7632));
        }
        #pragma unroll
        for (int i = 0; i < 8; i++) {
            int flat = t + i * 256;
            int ch = flat >> 5, px = flat & 31;
            float m = g_mean[b*CH + cb + ch], r = g_rstd[b*CH + cb + ch];
            float val = (xb[(size_t)(cb + ch) * NPIX + px] - m) * r;
            unsigned pk = split_pack(val);
            uint32_t off = (uint32_t)(px * SA + ch) * 2;
            *(unsigned short*)(dsm + B_HI + off) = (unsigned short)pk;
            *(unsigned short*)(dsm + B_LO + off) = (unsigned short)(pk >> 16);
        }
        __syncthreads();

        #pragma unroll
        for (int ks = 0; ks < 4; ks++) {
            const int k0 = ks * 16;
            uint32_t bh[4][2], bl[4][2];
            #pragma unroll
            for (int n = 0; n < 4; n++) {
                uint32_t bo = (uint32_t)(n * 8 * SA + k0 + boff) * 2;
                ldsm_x2(bh[n], smb + B_HI + bo);
                ldsm_x2(bl[n], smb + B_LO + bo);
            }
            #pragma unroll
            for (int m = 0; m < 4; m++) {
                uint32_t ah[4], al[4];
                uint32_t ao = (uint32_t)((w * 64 + m * 16) * SA + k0 + aoff) * 2;
                ldsm_x4(ah, smb + A_HI + ao);
                ldsm_x4(al, smb + A_LO + ao);
                #pragma unroll
                for (int n = 0; n < 4; n++) {
                    mma16816(acc[m][n], ah, bh[n]);
                    mma16816(acc[m][n], ah, bl[n]);
                    mma16816(acc[m][n], al, bh[n]);
                }
            }
        }
        __syncthreads();
    }

    // ---- epilogue stage 1: exp/pack K (+Z), pack V, split-bf16 into [256][SV] tiles ----
    if (w < 4) {
        #pragma unroll
        for (int m = 0; m < 4; m++) {
            int row = w * 64 + m * 16 + gid;
            float zr = 0.f, zr8 = 0.f;
            #pragma unroll
            for (int n = 0; n < 4; n++) {
                int px = n * 8 + 2 * tig;
                float e0 = expf(acc[m][n][0]);
                float e1 = expf(acc[m][n][1]);
                float e2 = expf(acc[m][n][2]);
                float e3 = expf(acc[m][n][3]);
                zr  += e0 + e1;
                zr8 += e2 + e3;
                unsigned p0 = split_pack(e0), p1 = split_pack(e1);
                unsigned p2 = split_pack(e2), p3 = split_pack(e3);
                *(unsigned*)(dsm + EK_HI + ( row      * SV + px) * 2) = __byte_perm(p0, p1, 0x5410);
                *(unsigned*)(dsm + EK_LO + ( row      * SV + px) * 2) = __byte_perm(p0, p1, 0x7632);
                *(unsigned*)(dsm + EK_HI + ((row + 8) * SV + px) * 2) = __byte_perm(p2, p3, 0x5410);
                *(unsigned*)(dsm + EK_LO + ((row + 8) * SV + px) * 2) = __byte_perm(p2, p3, 0x7632);
            }
            zr  += __shfl_xor_sync(0xFFFFFFFFu, zr, 1);
            zr  += __shfl_xor_sync(0xFFFFFFFFu, zr, 2);
            zr8 += __shfl_xor_sync(0xFFFFFFFFu, zr8, 1);
            zr8 += __shfl_xor_sync(0xFFFFFFFFu, zr8, 2);
            if (tig == 0) {
                atomicAdd(&g_Z[b*256 + row],     zr);
                atomicAdd(&g_Z[b*256 + row + 8], zr8);
            }
        }
    } else {
        #pragma unroll
        for (int m = 0; m < 4; m++) {
            int vr = w * 64 + m * 16 + gid - 256;
            #pragma unroll
            for (int n = 0; n < 4; n++) {
                int px = n * 8 + 2 * tig;
                unsigned p0 = split_pack(acc[m][n][0]), p1 = split_pack(acc[m][n][1]);
                unsigned p2 = split_pack(acc[m][n][2]), p3 = split_pack(acc[m][n][3]);
                *(unsigned*)(dsm + V_HI + ( vr      * SV + px) * 2) = __byte_perm(p0, p1, 0x5410);
                *(unsigned*)(dsm + V_LO + ( vr      * SV + px) * 2) = __byte_perm(p0, p1, 0x7632);
                *(unsigned*)(dsm + V_HI + ((vr + 8) * SV + px) * 2) = __byte_perm(p2, p3, 0x5410);
                *(unsigned*)(dsm + V_LO + ((vr + 8) * SV + px) * 2) = __byte_perm(p2, p3, 0x7632);
            }
        }
    }
    __syncthreads();

    // ---- epilogue stage 2: per-head S = ek · v^T via MMA (K = 32 px), atomicAdd ----
    {
        const int h = w;   // 8 warps = 8 heads
        const int aoff2 = ((seg & 1) * 8 + lrow) * SV + (seg >> 1) * 8;
        const int boff2 = (l2 & 7) * SV + (l2 >> 3) * 8;
        float sc[2][4][4];
        #pragma unroll
        for (int m = 0; m < 2; m++)
            #pragma unroll
            for (int n = 0; n < 4; n++)
                #pragma unroll
                for (int q = 0; q < 4; q++) sc[m][n][q] = 0.f;

        #pragma unroll
        for (int kk = 0; kk < 2; kk++) {
            const int k0 = kk * 16;
            uint32_t bh2[4][2], bl2[4][2];
            #pragma unroll
            for (int n = 0; n < 4; n++) {
                uint32_t bo = (uint32_t)((h*32 + n*8) * SV + k0 + boff2) * 2;
                ldsm_x2(bh2[n], smb + V_HI + bo);
                ldsm_x2(bl2[n], smb + V_LO + bo);
            }
            #pragma unroll
            for (int m = 0; m < 2; m++) {
                uint32_t ah[4], al[4];
                uint32_t ao = (uint32_t)((h*32 + m*16) * SV + k0 + aoff2) * 2;
                ldsm_x4(ah, smb + EK_HI + ao);
                ldsm_x4(al, smb + EK_LO + ao);
                #pragma unroll
                for (int n = 0; n < 4; n++) {
                    mma16816(sc[m][n], ah, bh2[n]);
                    mma16816(sc[m][n], ah, bl2[n]);
                    mma16816(sc[m][n], al, bh2[n]);
                }
            }
        }
        float* Sb = g_S + (size_t)(b*HEADS + h) * (DH*DH);
        #pragma unroll
        for (int m = 0; m < 2; m++) {
            int d = m*16 + gid;
            #pragma unroll
            for (int n = 0; n < 4; n++) {
                int e = n*8 + 2*tig;
                atomicAdd(&Sb[ d      * DH + e    ], sc[m][n][0]);
                atomicAdd(&Sb[ d      * DH + e + 1], sc[m][n][1]);
                atomicAdd(&Sb[(d + 8) * DH + e    ], sc[m][n][2]);
                atomicAdd(&Sb[(d + 8) * DH + e + 1], sc[m][n][3]);
            }
        }
    }
}

// ---------------- k_wf: finalize ctx, fold into W_out, write split-packed -----------
__global__ __launch_bounds__(256) void k_wf(const float* __restrict__ mem_kv,
                                            const float* __restrict__ w_out) {
    __shared__ float ctxsm[DH*DH];
    __shared__ float wsm[CH*33];
    const int h = blockIdx.x, b = blockIdx.y;
    const int t = threadIdx.x;
    {
        int d  = t >> 3;
        int e0 = (t & 7) * 4;
        float ekm[NMEM];
        float zm = 0.f;
        #pragma unroll
        for (int m = 0; m < NMEM; m++) {
            ekm[m] = expf(mem_kv[(h*DH + d)*NMEM + m]);
            zm += ekm[m];
        }
        float inv = 1.f / (g_Z[(b*HEADS + h)*DH + d] + zm);
        #pragma unroll
        for (int j = 0; j < 4; j++) {
            int e = e0 + j;
            float s = g_S[((size_t)(b*HEADS + h)*DH + d)*DH + e];
            float sm = 0.f;
            #pragma unroll
            for (int m = 0; m < NMEM; m++)
                sm = fmaf(ekm[m], mem_kv[HEADS*DH*NMEM + (h*DH + e)*NMEM + m], sm);
            ctxsm[d*DH + e] = (s + sm) * inv;
        }
    }
    #pragma unroll
    for (int i = 0; i < 8; i++) {
        int idx = t + i * 256;
        int c = idx >> 3, eq = (idx & 7) * 4;
        float4 wv = *(const float4*)(w_out + (size_t)c * CH + h*DH + eq);
        wsm[c*33 + eq+0] = wv.x; wsm[c*33 + eq+1] = wv.y;
        wsm[c*33 + eq+2] = wv.z; wsm[c*33 + eq+3] = wv.w;
    }
    __syncthreads();
    float acc[DH];
    #pragma unroll
    for (int d = 0; d < DH; d++) acc[d] = 0.f;
    for (int e = 0; e < DH; e++) {
        float wv = wsm[t*33 + e];
        #pragma unroll
        for (int d = 0; d < DH; d++)
            acc[d] = fmaf(wv, ctxsm[d*DH + e], acc[d]);
    }
    unsigned* dst = g_wfhl + ((size_t)b*CH + t)*CH + h*DH;
    #pragma unroll
    for (int d = 0; d < DH; d++) dst[d] = split_pack(acc[d]);
}

// ---------------- k_out_mma: HMMA q GEMM -> softmax -> HMMA Wf GEMM -> LN -> res ----
#define OX    0
#define OA_HI 36864
#define OA_LO 73728
#define OB_HI 110592
#define OB_LO 115200
#define OQ    119808
#define OUT_SMEM 156672

__global__ __launch_bounds__(256, 1) void k_out_mma(const float* __restrict__ x,
                                                    const float* __restrict__ b_out,
                                                    const float* __restrict__ ln_g,
                                                    float* __restrict__ out) {
    extern __shared__ char dsm[];
    __shared__ float colsum[8][32], colsq[8][32], mcol[32], rcol[32];
    const int b = blockIdx.y, pt = blockIdx.x;
    const int t = threadIdx.x, lane = t & 31, w = t >> 5;
    const uint32_t smb = smem_u32(dsm);
    float* X = (float*)(dsm + OX);
    float* Q = (float*)(dsm + OQ);

    const int p = t & 31, cb = t >> 5;
    const float* xb = x + (size_t)b * CH * NPIX + (size_t)pt * 32;

    #pragma unroll 4
    for (int i = 0; i < 32; i++) {
        int c = cb + i * 8;
        float xv = xb[(size_t)c * NPIX + p];
        X[c*36 + p] = (xv - g_mean[b*CH + c]) * g_rstd[b*CH + c];
    }
    __syncthreads();

    const int lrow = lane & 7, seg = lane >> 3;
    const int aoff = ((seg & 1) * 8 + lrow) * SA + (seg >> 1) * 8;
    const int l2 = lane & 15;
    const int boff = (l2 & 7) * SA + (l2 >> 3) * 8;
    const int gid = lane >> 2, tig = lane & 3;

    const uint4* wq4 = (const uint4*)g_whl;
    const uint4* wf4 = (const uint4*)(g_wfhl + (size_t)b * CH * CH);

    float acc[2][4][4];

    #pragma unroll 1
    for (int pass = 0; pass < 2; pass++) {
        const uint4* wsrc = pass ? wf4 : wq4;
        #pragma unroll
        for (int m = 0; m < 2; m++)
            #pragma unroll
            for (int n = 0; n < 4; n++)
                #pragma unroll
                for (int q = 0; q < 4; q++) acc[m][n][q] = 0.f;

        #pragma unroll 1
        for (int c = 0; c < 4; c++) {
            #pragma unroll
            for (int i = 0; i < 16; i++) {
                int flat = t + i * 256;
                int r = flat >> 4, q = flat & 15;
                uint4 u = wsrc[(size_t)r * 64 + c * 16 + q];
                uint32_t off = (uint32_t)r * (SA*2) + q * 8;
                *(uint2*)(dsm + OA_HI + off) = make_uint2(__byte_perm(u.x,u.y,0x5410), __byte_perm(u.z,u.w,0x5410));
                *(uint2*)(dsm + OA_LO + off) = make_uint2(__byte_perm(u.x,u.y,0x7632), __byte_perm(u.z,u.w,0x7632));
            }
            const float* src = pass ? Q : X;
            #pragma unroll
            for (int i = 0; i < 8; i++) {
                int flat = t + i * 256;
                int ch = flat >> 5, px = flat & 31;
                unsigned pk = split_pack(src[(c*64 + ch)*36 + px]);
                uint32_t off = (uint32_t)(px * SA + ch) * 2;
                *(unsigned short*)(dsm + OB_HI + off) = (unsigned short)pk;
                *(unsigned short*)(dsm + OB_LO + off) = (unsigned short)(pk >> 16);
            }
            __syncthreads();

            #pragma unroll
            for (int ks = 0; ks < 4; ks++) {
                const int k0 = ks * 16;
                uint32_t bh[4][2], bl[4][2];
                #pragma unroll
                for (int n = 0; n < 4; n++) {
                    uint32_t bo = (uint32_t)(n * 8 * SA + k0 + boff) * 2;
                    ldsm_x2(bh[n], smb + OB_HI + bo);
                    ldsm_x2(bl[n], smb + OB_LO + bo);
                }
                #pragma unroll
                for (int m = 0; m < 2; m++) {
                    uint32_t ah[4], al[4];
                    uint32_t ao = (uint32_t)((w * 32 + m * 16) * SA + k0 + aoff) * 2;
                    ldsm_x4(ah, smb + OA_HI + ao);
                    ldsm_x4(al, smb + OA_LO + ao);
                    #pragma unroll
                    for (int n = 0; n < 4; n++) {
                        mma16816(acc[m][n], ah, bh[n]);
                        mma16816(acc[m][n], ah, bl[n]);
                        mma16816(acc[m][n], al, bh[n]);
                    }
                }
            }
            __syncthreads();
        }

        if (pass == 0) {
            #pragma unroll
            for (int m = 0; m < 2; m++) {
                int row = w * 32 + m * 16 + gid;
                #pragma unroll
                for (int n = 0; n < 4; n++) {
                    int px = n * 8 + 2 * tig;
                    Q[ row      * 36 + px    ] = acc[m][n][0];
                    Q[ row      * 36 + px + 1] = acc[m][n][1];
                    Q[(row + 8) * 36 + px    ] = acc[m][n][2];
                    Q[(row + 8) * 36 + px + 1] = acc[m][n][3];
                }
            }
            __syncthreads();
            {
                float* qc = Q + (size_t)(cb * 32) * 36 + p;
                float vals[32];
                float mx = -1e30f;
                #pragma unroll
                for (int dd = 0; dd < 32; dd++) { vals[dd] = qc[dd*36]; mx = fmaxf(mx, vals[dd]); }
                float s = 0.f;
                #pragma unroll
                for (int dd = 0; dd < 32; dd++) { vals[dd] = expf(vals[dd] - mx); s += vals[dd]; }
                float inv = SCALE_Q / s;
                #pragma unroll
                for (int dd = 0; dd < 32; dd++) qc[dd*36] = vals[dd] * inv;
            }
            __syncthreads();
        }
    }

    #pragma unroll
    for (int m = 0; m < 2; m++) {
        int row = w * 32 + m * 16 + gid;
        float bo0 = b_out[row], bo8 = b_out[row + 8];
        #pragma unroll
        for (int n = 0; n < 4; n++) {
            int px = n * 8 + 2 * tig;
            Q[ row      * 36 + px    ] = acc[m][n][0] + bo0;
            Q[ row      * 36 + px + 1] = acc[m][n][1] + bo0;
            Q[(row + 8) * 36 + px    ] = acc[m][n][2] + bo8;
            Q[(row + 8) * 36 + px + 1] = acc[m][n][3] + bo8;
        }
    }
    __syncthreads();

    {
        float ps = 0.f, pq = 0.f;
        for (int i = 0; i < 32; i++) {
            float v = Q[(cb*32 + i)*36 + p];
            ps += v; pq += v * v;
        }
        colsum[cb][p] = ps; colsq[cb][p] = pq;
    }
    __syncthreads();
    if (t < 32) {
        float s = 0.f, q2 = 0.f;
        #pragma unroll
        for (int sg = 0; sg < 8; sg++) { s += colsum[sg][t]; q2 += colsq[sg][t]; }
        float m   = s * (1.f / 256.f);
        float var = q2 * (1.f / 256.f) - m * m;
        mcol[t] = m;
        rcol[t] = rsqrtf(var + LN_EPS);
    }
    __syncthreads();
    float* ob = out + (size_t)b * CH * NPIX + (size_t)pt * 32;
    #pragma unroll 4
    for (int i = 0; i < 32; i++) {
        int c = cb + i * 8;
        float v = (Q[c*36 + p] - mcol[p]) * rcol[p] * ln_g[c] + X[c*36 + p];
        ob[(size_t)c * NPIX + p] = v;
    }
}

// ---------------- launch ----------------
extern "C" void kernel_launch(void* const* d_in, const int* in_sizes, int n_in,
                              void* d_out, int out_size) {
    const float* x      = (const float*)d_in[0];
    const float* w_qkv  = (const float*)d_in[1];
    const float* mem_kv = (const float*)d_in[2];
    const float* w_out  = (const float*)d_in[3];
    const float* b_out  = (const float*)d_in[4];
    const float* ln_g   = (const float*)d_in[5];
    float* out = (float*)d_out;

    cudaFuncSetAttribute(k_kv_mma,  cudaFuncAttributeMaxDynamicSharedMemorySize, KV_SMEM);
    cudaFuncSetAttribute(k_out_mma, cudaFuncAttributeMaxDynamicSharedMemorySize, OUT_SMEM);

    k_zero<<<512, 256>>>();
    k_stats<<<BATCH * CH, 256>>>(x);
    k_wprep<<<768, 256>>>(w_qkv);
    k_kv_mma<<<dim3(NPIX/32, BATCH), 256, KV_SMEM>>>(x);
    k_wf<<<dim3(HEADS, BATCH), 256>>>(mem_kv, w_out);
    k_out_mma<<<dim3(NPIX/32, BATCH), 256, OUT_SMEM>>>(x, b_out, ln_g, out);
}

// round 11
// speedup vs baseline: 1.9426x; 1.0711x over previous
#include <cuda_runtime.h>
#include <cuda_bf16.h>
#include <math.h>
#include <stdint.h>

#define BATCH 16
#define CH    256
#define NPIX  16384
#define HEADS 8
#define DH    32
#define NMEM  4
#define SCALE_Q 0.5f
#define LN_EPS 1e-5f

// ---------------- helpers ----------------
__device__ __forceinline__ uint32_t smem_u32(const void* p) {
    uint32_t a;
    asm("{ .reg .u64 t; cvta.to.shared.u64 t, %1; cvt.u32.u64 %0, t; }" : "=r"(a) : "l"(p));
    return a;
}
__device__ __forceinline__ void ldsm_x4(uint32_t* r, uint32_t addr) {
    asm volatile("ldmatrix.sync.aligned.m8n8.x4.shared.b16 {%0,%1,%2,%3}, [%4];"
        : "=r"(r[0]), "=r"(r[1]), "=r"(r[2]), "=r"(r[3]) : "r"(addr));
}
__device__ __forceinline__ void ldsm_x2(uint32_t* r, uint32_t addr) {
    asm volatile("ldmatrix.sync.aligned.m8n8.x2.shared.b16 {%0,%1}, [%2];"
        : "=r"(r[0]), "=r"(r[1]) : "r"(addr));
}
__device__ __forceinline__ void mma16816(float* c, const uint32_t* a, const uint32_t* b) {
    asm volatile("mma.sync.aligned.m16n8k16.row.col.f32.bf16.bf16.f32 "
        "{%0,%1,%2,%3}, {%4,%5,%6,%7}, {%8,%9}, {%0,%1,%2,%3};"
        : "+f"(c[0]), "+f"(c[1]), "+f"(c[2]), "+f"(c[3])
        : "r"(a[0]), "r"(a[1]), "r"(a[2]), "r"(a[3]), "r"(b[0]), "r"(b[1]));
}
__device__ __forceinline__ unsigned split_pack(float v) {
    unsigned short h = __bfloat16_as_ushort(__float2bfloat16(v));
    float hf = __bfloat162float(__ushort_as_bfloat16(h));
    unsigned short l = __bfloat16_as_ushort(__float2bfloat16(v - hf));
    return (unsigned)h | ((unsigned)l << 16);
}

// ---------------- scratch ----------------
__device__ float g_mean[BATCH*CH];
__device__ float g_rstd[BATCH*CH];
__device__ float g_S[BATCH*HEADS*DH*DH];
__device__ float g_Z[BATCH*HEADS*DH];
__device__ unsigned g_whl[768*CH];             // split-packed w_qkv
__device__ unsigned g_wfhl[BATCH*CH*CH];       // split-packed fused Wf (per batch)

// ---------------- k_zero ----------------
__global__ void k_zero() {
    int i = blockIdx.x * 256 + threadIdx.x;
    if (i < BATCH*HEADS*DH*DH) g_S[i] = 0.f;
    if (i < BATCH*HEADS*DH)    g_Z[i] = 0.f;
}

// ---------------- k_stats ----------------
__global__ __launch_bounds__(256) void k_stats(const float* __restrict__ x) {
    int bc = blockIdx.x;
    const float4* p = (const float4*)(x + (size_t)bc * NPIX);
    float s = 0.f, ss = 0.f;
    for (int i = threadIdx.x; i < NPIX/4; i += 256) {
        float4 v = p[i];
        s  += v.x + v.y + v.z + v.w;
        ss += v.x*v.x + v.y*v.y + v.z*v.z + v.w*v.w;
    }
    __shared__ float rs[256], rq[256];
    rs[threadIdx.x] = s; rq[threadIdx.x] = ss;
    __syncthreads();
    for (int o = 128; o > 0; o >>= 1) {
        if (threadIdx.x < o) { rs[threadIdx.x] += rs[threadIdx.x+o]; rq[threadIdx.x] += rq[threadIdx.x+o]; }
        __syncthreads();
    }
    if (threadIdx.x == 0) {
        float m   = rs[0] * (1.f / NPIX);
        float var = rq[0] * (1.f / NPIX) - m * m;
        g_mean[bc] = m;
        g_rstd[bc] = rsqrtf(var + LN_EPS);
    }
}

// ---------------- k_wprep ----------------
__global__ void k_wprep(const float* __restrict__ w_qkv) {
    int i = blockIdx.x * 256 + threadIdx.x;
    g_whl[i] = split_pack(w_qkv[i]);
}

// ---------------- k_kv_mma: 64-px tile, 512 threads, HMMA + MMA S-epilogue --------
#define SA 72
#define A_HI 0
#define A_LO 73728
#define B_HI 147456
#define B_LO 156672
#define KV_SMEM 165888
// epilogue alias (bf16 split, 64 px + pad -> stride 72)
#define SV 72
#define EK_HI 0
#define EK_LO 36864
#define V_HI  73728
#define V_LO  110592

__global__ __launch_bounds__(512, 1) void k_kv_mma(const float* __restrict__ x) {
    extern __shared__ char dsm[];
    const int b = blockIdx.y, pt = blockIdx.x;
    const int t = threadIdx.x, lane = t & 31, w = t >> 5;
    const uint32_t smb = smem_u32(dsm);

    const int px0 = pt * 64;
    const float* xb = x + (size_t)b * CH * NPIX + px0;
    const uint4* whl4 = (const uint4*)(g_whl + 256 * CH);

    const int lrow = lane & 7, seg = lane >> 3;
    const int aoff = ((seg & 1) * 8 + lrow) * SA + (seg >> 1) * 8;
    const int l2 = lane & 15;
    const int boff = (l2 & 7) * SA + (l2 >> 3) * 8;
    const int gid = lane >> 2, tig = lane & 3;

    const int rw = w & 7;        // row-slice warp id (64 rows each)
    const int ph = w >> 3;       // px half (0 or 1)
    const int pb = ph * 32;      // px base within tile

    float acc[4][4][4];
    #pragma unroll
    for (int m = 0; m < 4; m++)
        #pragma unroll
        for (int n = 0; n < 4; n++)
            #pragma unroll
            for (int q = 0; q < 4; q++) acc[m][n][q] = 0.f;

    for (int c = 0; c < 4; c++) {
        const int cb = c * 64;
        // A chunk: 512 rows x 64 ch (uint4 = 4 ch), 16 per thread
        #pragma unroll
        for (int i = 0; i < 16; i++) {
            int flat = t + i * 512;
            int r = flat >> 4, q = flat & 15;
            uint4 u = whl4[(size_t)r * 64 + c * 16 + q];
            uint32_t off = (uint32_t)r * (SA*2) + q * 8;
            *(uint2*)(dsm + A_HI + off) = make_uint2(__byte_perm(u.x,u.y,0x5410), __byte_perm(u.z,u.w,0x5410));
            *(uint2*)(dsm + A_LO + off) = make_uint2(__byte_perm(u.x,u.y,0x7632), __byte_perm(u.z,u.w,0x7632));
        }
        // B chunk: xn [64 ch][64 px] -> Bt[px][ch], 8 per thread
        #pragma unroll
        for (int i = 0; i < 8; i++) {
            int flat = t + i * 512;          // 0..4095
            int ch = flat >> 6, px = flat & 63;
            float m = g_mean[b*CH + cb + ch], r = g_rstd[b*CH + cb + ch];
            float val = (xb[(size_t)(cb + ch) * NPIX + px] - m) * r;
            unsigned pk = split_pack(val);
            uint32_t off = (uint32_t)(px * SA + ch) * 2;
            *(unsigned short*)(dsm + B_HI + off) = (unsigned short)pk;
            *(unsigned short*)(dsm + B_LO + off) = (unsigned short)(pk >> 16);
        }
        __syncthreads();

        #pragma unroll
        for (int ks = 0; ks < 4; ks++) {
            const int k0 = ks * 16;
            uint32_t bh[4][2], bl[4][2];
            #pragma unroll
            for (int n = 0; n < 4; n++) {
                uint32_t bo = (uint32_t)((pb + n * 8) * SA + k0 + boff) * 2;
                ldsm_x2(bh[n], smb + B_HI + bo);
                ldsm_x2(bl[n], smb + B_LO + bo);
            }
            #pragma unroll
            for (int m = 0; m < 4; m++) {
                uint32_t ah[4], al[4];
                uint32_t ao = (uint32_t)((rw * 64 + m * 16) * SA + k0 + aoff) * 2;
                ldsm_x4(ah, smb + A_HI + ao);
                ldsm_x4(al, smb + A_LO + ao);
                #pragma unroll
                for (int n = 0; n < 4; n++) {
                    mma16816(acc[m][n], ah, bh[n]);
                    mma16816(acc[m][n], ah, bl[n]);
                    mma16816(acc[m][n], al, bh[n]);
                }
            }
        }
        __syncthreads();
    }

    // ---- epilogue stage 1: exp/pack K (+Z), pack V into [256][SV] split tiles ----
    if (rw < 4) {
        #pragma unroll
        for (int m = 0; m < 4; m++) {
            int row = rw * 64 + m * 16 + gid;
            float zr = 0.f, zr8 = 0.f;
            #pragma unroll
            for (int n = 0; n < 4; n++) {
                int px = pb + n * 8 + 2 * tig;
                float e0 = expf(acc[m][n][0]);
                float e1 = expf(acc[m][n][1]);
                float e2 = expf(acc[m][n][2]);
                float e3 = expf(acc[m][n][3]);
                zr  += e0 + e1;
                zr8 += e2 + e3;
                unsigned p0 = split_pack(e0), p1 = split_pack(e1);
                unsigned p2 = split_pack(e2), p3 = split_pack(e3);
                *(unsigned*)(dsm + EK_HI + ( row      * SV + px) * 2) = __byte_perm(p0, p1, 0x5410);
                *(unsigned*)(dsm + EK_LO + ( row      * SV + px) * 2) = __byte_perm(p0, p1, 0x7632);
                *(unsigned*)(dsm + EK_HI + ((row + 8) * SV + px) * 2) = __byte_perm(p2, p3, 0x5410);
                *(unsigned*)(dsm + EK_LO + ((row + 8) * SV + px) * 2) = __byte_perm(p2, p3, 0x7632);
            }
            zr  += __shfl_xor_sync(0xFFFFFFFFu, zr, 1);
            zr  += __shfl_xor_sync(0xFFFFFFFFu, zr, 2);
            zr8 += __shfl_xor_sync(0xFFFFFFFFu, zr8, 1);
            zr8 += __shfl_xor_sync(0xFFFFFFFFu, zr8, 2);
            if (tig == 0) {
                atomicAdd(&g_Z[b*256 + row],     zr);
                atomicAdd(&g_Z[b*256 + row + 8], zr8);
            }
        }
    } else {
        #pragma unroll
        for (int m = 0; m < 4; m++) {
            int vr = (rw - 4) * 64 + m * 16 + gid;
            #pragma unroll
            for (int n = 0; n < 4; n++) {
                int px = pb + n * 8 + 2 * tig;
                unsigned p0 = split_pack(acc[m][n][0]), p1 = split_pack(acc[m][n][1]);
                unsigned p2 = split_pack(acc[m][n][2]), p3 = split_pack(acc[m][n][3]);
                *(unsigned*)(dsm + V_HI + ( vr      * SV + px) * 2) = __byte_perm(p0, p1, 0x5410);
                *(unsigned*)(dsm + V_LO + ( vr      * SV + px) * 2) = __byte_perm(p0, p1, 0x7632);
                *(unsigned*)(dsm + V_HI + ((vr + 8) * SV + px) * 2) = __byte_perm(p2, p3, 0x5410);
                *(unsigned*)(dsm + V_LO + ((vr + 8) * SV + px) * 2) = __byte_perm(p2, p3, 0x7632);
            }
        }
    }
    __syncthreads();

    // ---- epilogue stage 2: S = ek · v^T via MMA; 2 warps per head (K=32 each) ----
    {
        const int h  = w & 7;          // head
        const int kb = (w >> 3) * 32;  // K (pixel) base for this warp
        const int aoff2 = ((seg & 1) * 8 + lrow) * SV + (seg >> 1) * 8;
        const int boff2 = (l2 & 7) * SV + (l2 >> 3) * 8;
        float sc[2][4][4];
        #pragma unroll
        for (int m = 0; m < 2; m++)
            #pragma unroll
            for (int n = 0; n < 4; n++)
                #pragma unroll
                for (int q = 0; q < 4; q++) sc[m][n][q] = 0.f;

        #pragma unroll
        for (int kk = 0; kk < 2; kk++) {
            const int k0 = kb + kk * 16;
            uint32_t bh2[4][2], bl2[4][2];
            #pragma unroll
            for (int n = 0; n < 4; n++) {
                uint32_t bo = (uint32_t)((h*32 + n*8) * SV + k0 + boff2) * 2;
                ldsm_x2(bh2[n], smb + V_HI + bo);
                ldsm_x2(bl2[n], smb + V_LO + bo);
            }
            #pragma unroll
            for (int m = 0; m < 2; m++) {
                uint32_t ah[4], al[4];
                uint32_t ao = (uint32_t)((h*32 + m*16) * SV + k0 + aoff2) * 2;
                ldsm_x4(ah, smb + EK_HI + ao);
                ldsm_x4(al, smb + EK_LO + ao);
                #pragma unroll
                for (int n = 0; n < 4; n++) {
                    mma16816(sc[m][n], ah, bh2[n]);
                    mma16816(sc[m][n], ah, bl2[n]);
                    mma16816(sc[m][n], al, bh2[n]);
                }
            }
        }
        float* Sb = g_S + (size_t)(b*HEADS + h) * (DH*DH);
        #pragma unroll
        for (int m = 0; m < 2; m++) {
            int d = m*16 + gid;
            #pragma unroll
            for (int n = 0; n < 4; n++) {
                int e = n*8 + 2*tig;
                atomicAdd(&Sb[ d      * DH + e    ], sc[m][n][0]);
                atomicAdd(&Sb[ d      * DH + e + 1], sc[m][n][1]);
                atomicAdd(&Sb[(d + 8) * DH + e    ], sc[m][n][2]);
                atomicAdd(&Sb[(d + 8) * DH + e + 1], sc[m][n][3]);
            }
        }
    }
}

// ---------------- k_wf: finalize ctx, fold into W_out, write split-packed -----------
__global__ __launch_bounds__(256) void k_wf(const float* __restrict__ mem_kv,
                                            const float* __restrict__ w_out) {
    __shared__ float ctxsm[DH*DH];
    __shared__ float wsm[CH*33];
    const int h = blockIdx.x, b = blockIdx.y;
    const int t = threadIdx.x;
    {
        int d  = t >> 3;
        int e0 = (t & 7) * 4;
        float ekm[NMEM];
        float zm = 0.f;
        #pragma unroll
        for (int m = 0; m < NMEM; m++) {
            ekm[m] = expf(mem_kv[(h*DH + d)*NMEM + m]);
            zm += ekm[m];
        }
        float inv = 1.f / (g_Z[(b*HEADS + h)*DH + d] + zm);
        #pragma unroll
        for (int j = 0; j < 4; j++) {
            int e = e0 + j;
            float s = g_S[((size_t)(b*HEADS + h)*DH + d)*DH + e];
            float sm = 0.f;
            #pragma unroll
            for (int m = 0; m < NMEM; m++)
                sm = fmaf(ekm[m], mem_kv[HEADS*DH*NMEM + (h*DH + e)*NMEM + m], sm);
            ctxsm[d*DH + e] = (s + sm) * inv;
        }
    }
    #pragma unroll
    for (int i = 0; i < 8; i++) {
        int idx = t + i * 256;
        int c = idx >> 3, eq = (idx & 7) * 4;
        float4 wv = *(const float4*)(w_out + (size_t)c * CH + h*DH + eq);
        wsm[c*33 + eq+0] = wv.x; wsm[c*33 + eq+1] = wv.y;
        wsm[c*33 + eq+2] = wv.z; wsm[c*33 + eq+3] = wv.w;
    }
    __syncthreads();
    float acc[DH];
    #pragma unroll
    for (int d = 0; d < DH; d++) acc[d] = 0.f;
    for (int e = 0; e < DH; e++) {
        float wv = wsm[t*33 + e];
        #pragma unroll
        for (int d = 0; d < DH; d++)
            acc[d] = fmaf(wv, ctxsm[d*DH + e], acc[d]);
    }
    unsigned* dst = g_wfhl + ((size_t)b*CH + t)*CH + h*DH;
    #pragma unroll
    for (int d = 0; d < DH; d++) dst[d] = split_pack(acc[d]);
}

// ---------------- k_out_mma: HMMA q GEMM -> softmax -> HMMA Wf GEMM -> LN -> res ----
#define OX    0
#define OA_HI 36864
#define OA_LO 73728
#define OB_HI 110592
#define OB_LO 115200
#define OQ    119808
#define OUT_SMEM 156672

__global__ __launch_bounds__(256, 1) void k_out_mma(const float* __restrict__ x,
                                                    const float* __restrict__ b_out,
                                                    const float* __restrict__ ln_g,
                                                    float* __restrict__ out) {
    extern __shared__ char dsm[];
    __shared__ float colsum[8][32], colsq[8][32], mcol[32], rcol[32];
    const int b = blockIdx.y, pt = blockIdx.x;
    const int t = threadIdx.x, lane = t & 31, w = t >> 5;
    const uint32_t smb = smem_u32(dsm);
    float* X = (float*)(dsm + OX);
    float* Q = (float*)(dsm + OQ);

    const int p = t & 31, cb = t >> 5;
    const float* xb = x + (size_t)b * CH * NPIX + (size_t)pt * 32;

    #pragma unroll 4
    for (int i = 0; i < 32; i++) {
        int c = cb + i * 8;
        float xv = xb[(size_t)c * NPIX + p];
        X[c*36 + p] = (xv - g_mean[b*CH + c]) * g_rstd[b*CH + c];
    }
    __syncthreads();

    const int lrow = lane & 7, seg = lane >> 3;
    const int aoff = ((seg & 1) * 8 + lrow) * SA + (seg >> 1) * 8;
    const int l2 = lane & 15;
    const int boff = (l2 & 7) * SA + (l2 >> 3) * 8;
    const int gid = lane >> 2, tig = lane & 3;

    const uint4* wq4 = (const uint4*)g_whl;
    const uint4* wf4 = (const uint4*)(g_wfhl + (size_t)b * CH * CH);

    float acc[2][4][4];

    #pragma unroll 1
    for (int pass = 0; pass < 2; pass++) {
        const uint4* wsrc = pass ? wf4 : wq4;
        #pragma unroll
        for (int m = 0; m < 2; m++)
            #pragma unroll
            for (int n = 0; n < 4; n++)
                #pragma unroll
                for (int q = 0; q < 4; q++) acc[m][n][q] = 0.f;

        #pragma unroll 1
        for (int c = 0; c < 4; c++) {
            #pragma unroll
            for (int i = 0; i < 16; i++) {
                int flat = t + i * 256;
                int r = flat >> 4, q = flat & 15;
                uint4 u = wsrc[(size_t)r * 64 + c * 16 + q];
                uint32_t off = (uint32_t)r * (SA*2) + q * 8;
                *(uint2*)(dsm + OA_HI + off) = make_uint2(__byte_perm(u.x,u.y,0x5410), __byte_perm(u.z,u.w,0x5410));
                *(uint2*)(dsm + OA_LO + off) = make_uint2(__byte_perm(u.x,u.y,0x7632), __byte_perm(u.z,u.w,0x7632));
            }
            const float* src = pass ? Q : X;
            #pragma unroll
            for (int i = 0; i < 8; i++) {
                int flat = t + i * 256;
                int ch = flat >> 5, px = flat & 31;
                unsigned pk = split_pack(src[(c*64 + ch)*36 + px]);
                uint32_t off = (uint32_t)(px * SA + ch) * 2;
                *(unsigned short*)(dsm + OB_HI + off) = (unsigned short)pk;
                *(unsigned short*)(dsm + OB_LO + off) = (unsigned short)(pk >> 16);
            }
            __syncthreads();

            #pragma unroll
            for (int ks = 0; ks < 4; ks++) {
                const int k0 = ks * 16;
                uint32_t bh[4][2], bl[4][2];
                #pragma unroll
                for (int n = 0; n < 4; n++) {
                    uint32_t bo = (uint32_t)(n * 8 * SA + k0 + boff) * 2;
                    ldsm_x2(bh[n], smb + OB_HI + bo);
                    ldsm_x2(bl[n], smb + OB_LO + bo);
                }
                #pragma unroll
                for (int m = 0; m < 2; m++) {
                    uint32_t ah[4], al[4];
                    uint32_t ao = (uint32_t)((w * 32 + m * 16) * SA + k0 + aoff) * 2;
                    ldsm_x4(ah, smb + OA_HI + ao);
                    ldsm_x4(al, smb + OA_LO + ao);
                    #pragma unroll
                    for (int n = 0; n < 4; n++) {
                        mma16816(acc[m][n], ah, bh[n]);
                        mma16816(acc[m][n], ah, bl[n]);
                        mma16816(acc[m][n], al, bh[n]);
                    }
                }
            }
            __syncthreads();
        }

        if (pass == 0) {
            #pragma unroll
            for (int m = 0; m < 2; m++) {
                int row = w * 32 + m * 16 + gid;
                #pragma unroll
                for (int n = 0; n < 4; n++) {
                    int px = n * 8 + 2 * tig;
                    Q[ row      * 36 + px    ] = acc[m][n][0];
                    Q[ row      * 36 + px + 1] = acc[m][n][1];
                    Q[(row + 8) * 36 + px    ] = acc[m][n][2];
                    Q[(row + 8) * 36 + px + 1] = acc[m][n][3];
                }
            }
            __syncthreads();
            {
                float* qc = Q + (size_t)(cb * 32) * 36 + p;
                float vals[32];
                float mx = -1e30f;
                #pragma unroll
                for (int dd = 0; dd < 32; dd++) { vals[dd] = qc[dd*36]; mx = fmaxf(mx, vals[dd]); }
                float s = 0.f;
                #pragma unroll
                for (int dd = 0; dd < 32; dd++) { vals[dd] = expf(vals[dd] - mx); s += vals[dd]; }
                float inv = SCALE_Q / s;
                #pragma unroll
                for (int dd = 0; dd < 32; dd++) qc[dd*36] = vals[dd] * inv;
            }
            __syncthreads();
        }
    }

    #pragma unroll
    for (int m = 0; m < 2; m++) {
        int row = w * 32 + m * 16 + gid;
        float bo0 = b_out[row], bo8 = b_out[row + 8];
        #pragma unroll
        for (int n = 0; n < 4; n++) {
            int px = n * 8 + 2 * tig;
            Q[ row      * 36 + px    ] = acc[m][n][0] + bo0;
            Q[ row      * 36 + px + 1] = acc[m][n][1] + bo0;
            Q[(row + 8) * 36 + px    ] = acc[m][n][2] + bo8;
            Q[(row + 8) * 36 + px + 1] = acc[m][n][3] + bo8;
        }
    }
    __syncthreads();

    {
        float ps = 0.f, pq = 0.f;
        for (int i = 0; i < 32; i++) {
            float v = Q[(cb*32 + i)*36 + p];
            ps += v; pq += v * v;
        }
        colsum[cb][p] = ps; colsq[cb][p] = pq;
    }
    __syncthreads();
    if (t < 32) {
        float s = 0.f, q2 = 0.f;
        #pragma unroll
        for (int sg = 0; sg < 8; sg++) { s += colsum[sg][t]; q2 += colsq[sg][t]; }
        float m   = s * (1.f / 256.f);
        float var = q2 * (1.f / 256.f) - m * m;
        mcol[t] = m;
        rcol[t] = rsqrtf(var + LN_EPS);
    }
    __syncthreads();
    float* ob = out + (size_t)b * CH * NPIX + (size_t)pt * 32;
    #pragma unroll 4
    for (int i = 0; i < 32; i++) {
        int c = cb + i * 8;
        float v = (Q[c*36 + p] - mcol[p]) * rcol[p] * ln_g[c] + X[c*36 + p];
        ob[(size_t)c * NPIX + p] = v;
    }
}

// ---------------- launch ----------------
extern "C" void kernel_launch(void* const* d_in, const int* in_sizes, int n_in,
                              void* d_out, int out_size) {
    const float* x      = (const float*)d_in[0];
    const float* w_qkv  = (const float*)d_in[1];
    const float* mem_kv = (const float*)d_in[2];
    const float* w_out  = (const float*)d_in[3];
    const float* b_out  = (const float*)d_in[4];
    const float* ln_g   = (const float*)d_in[5];
    float* out = (float*)d_out;

    cudaFuncSetAttribute(k_kv_mma,  cudaFuncAttributeMaxDynamicSharedMemorySize, KV_SMEM);
    cudaFuncSetAttribute(k_out_mma, cudaFuncAttributeMaxDynamicSharedMemorySize, OUT_SMEM);

    k_zero<<<512, 256>>>();
    k_stats<<<BATCH * CH, 256>>>(x);
    k_wprep<<<768, 256>>>(w_qkv);
    k_kv_mma<<<dim3(NPIX/64, BATCH), 512, KV_SMEM>>>(x);
    k_wf<<<dim3(HEADS, BATCH), 256>>>(mem_kv, w_out);
    k_out_mma<<<dim3(NPIX/32, BATCH), 256, OUT_SMEM>>>(x, b_out, ln_g, out);
}

// round 12
// speedup vs baseline: 2.3970x; 1.2339x over previous
#include <cuda_runtime.h>
#include <cuda_bf16.h>
#include <math.h>
#include <stdint.h>

#define BATCH 16
#define CH    256
#define NPIX  16384
#define HEADS 8
#define DH    32
#define NMEM  4
#define SCALE_Q 0.5f
#define LN_EPS 1e-5f

// ---------------- helpers ----------------
__device__ __forceinline__ uint32_t smem_u32(const void* p) {
    uint32_t a;
    asm("{ .reg .u64 t; cvta.to.shared.u64 t, %1; cvt.u32.u64 %0, t; }" : "=r"(a) : "l"(p));
    return a;
}
__device__ __forceinline__ void ldsm_x4(uint32_t* r, uint32_t addr) {
    asm volatile("ldmatrix.sync.aligned.m8n8.x4.shared.b16 {%0,%1,%2,%3}, [%4];"
        : "=r"(r[0]), "=r"(r[1]), "=r"(r[2]), "=r"(r[3]) : "r"(addr));
}
__device__ __forceinline__ void ldsm_x2(uint32_t* r, uint32_t addr) {
    asm volatile("ldmatrix.sync.aligned.m8n8.x2.shared.b16 {%0,%1}, [%2];"
        : "=r"(r[0]), "=r"(r[1]) : "r"(addr));
}
__device__ __forceinline__ void mma16816(float* c, const uint32_t* a, const uint32_t* b) {
    asm volatile("mma.sync.aligned.m16n8k16.row.col.f32.bf16.bf16.f32 "
        "{%0,%1,%2,%3}, {%4,%5,%6,%7}, {%8,%9}, {%0,%1,%2,%3};"
        : "+f"(c[0]), "+f"(c[1]), "+f"(c[2]), "+f"(c[3])
        : "r"(a[0]), "r"(a[1]), "r"(a[2]), "r"(a[3]), "r"(b[0]), "r"(b[1]));
}
__device__ __forceinline__ unsigned split_pack(float v) {
    unsigned short h = __bfloat16_as_ushort(__float2bfloat16(v));
    float hf = __bfloat162float(__ushort_as_bfloat16(h));
    unsigned short l = __bfloat16_as_ushort(__float2bfloat16(v - hf));
    return (unsigned)h | ((unsigned)l << 16);
}

// ---------------- scratch ----------------
__device__ float g_mean[BATCH*CH];
__device__ float g_rstd[BATCH*CH];
__device__ float g_S[BATCH*HEADS*DH*DH];
__device__ float g_Z[BATCH*HEADS*DH];
__device__ unsigned g_whl[768*CH];             // split-packed w_qkv
__device__ unsigned g_wfhl[BATCH*CH*CH];       // split-packed fused Wf (per batch)

// ---------------- k_zero ----------------
__global__ void k_zero() {
    int i = blockIdx.x * 256 + threadIdx.x;
    if (i < BATCH*HEADS*DH*DH) g_S[i] = 0.f;
    if (i < BATCH*HEADS*DH)    g_Z[i] = 0.f;
}

// ---------------- k_stats ----------------
__global__ __launch_bounds__(256) void k_stats(const float* __restrict__ x) {
    int bc = blockIdx.x;
    const float4* p = (const float4*)(x + (size_t)bc * NPIX);
    float s = 0.f, ss = 0.f;
    for (int i = threadIdx.x; i < NPIX/4; i += 256) {
        float4 v = p[i];
        s  += v.x + v.y + v.z + v.w;
        ss += v.x*v.x + v.y*v.y + v.z*v.z + v.w*v.w;
    }
    __shared__ float rs[256], rq[256];
    rs[threadIdx.x] = s; rq[threadIdx.x] = ss;
    __syncthreads();
    for (int o = 128; o > 0; o >>= 1) {
        if (threadIdx.x < o) { rs[threadIdx.x] += rs[threadIdx.x+o]; rq[threadIdx.x] += rq[threadIdx.x+o]; }
        __syncthreads();
    }
    if (threadIdx.x == 0) {
        float m   = rs[0] * (1.f / NPIX);
        float var = rq[0] * (1.f / NPIX) - m * m;
        g_mean[bc] = m;
        g_rstd[bc] = rsqrtf(var + LN_EPS);
    }
}

// ---------------- k_wprep ----------------
__global__ void k_wprep(const float* __restrict__ w_qkv) {
    int i = blockIdx.x * 256 + threadIdx.x;
    g_whl[i] = split_pack(w_qkv[i]);
}

// ---------------- k_kv_mma: 64-px tile, 512 threads (unchanged from R11) ----------
#define SA 72
#define A_HI 0
#define A_LO 73728
#define B_HI 147456
#define B_LO 156672
#define KV_SMEM 165888
#define SV 72
#define EK_HI 0
#define EK_LO 36864
#define V_HI  73728
#define V_LO  110592

__global__ __launch_bounds__(512, 1) void k_kv_mma(const float* __restrict__ x) {
    extern __shared__ char dsm[];
    const int b = blockIdx.y, pt = blockIdx.x;
    const int t = threadIdx.x, lane = t & 31, w = t >> 5;
    const uint32_t smb = smem_u32(dsm);

    const int px0 = pt * 64;
    const float* xb = x + (size_t)b * CH * NPIX + px0;
    const uint4* whl4 = (const uint4*)(g_whl + 256 * CH);

    const int lrow = lane & 7, seg = lane >> 3;
    const int aoff = ((seg & 1) * 8 + lrow) * SA + (seg >> 1) * 8;
    const int l2 = lane & 15;
    const int boff = (l2 & 7) * SA + (l2 >> 3) * 8;
    const int gid = lane >> 2, tig = lane & 3;

    const int rw = w & 7;
    const int ph = w >> 3;
    const int pb = ph * 32;

    float acc[4][4][4];
    #pragma unroll
    for (int m = 0; m < 4; m++)
        #pragma unroll
        for (int n = 0; n < 4; n++)
            #pragma unroll
            for (int q = 0; q < 4; q++) acc[m][n][q] = 0.f;

    for (int c = 0; c < 4; c++) {
        const int cb = c * 64;
        #pragma unroll
        for (int i = 0; i < 16; i++) {
            int flat = t + i * 512;
            int r = flat >> 4, q = flat & 15;
            uint4 u = whl4[(size_t)r * 64 + c * 16 + q];
            uint32_t off = (uint32_t)r * (SA*2) + q * 8;
            *(uint2*)(dsm + A_HI + off) = make_uint2(__byte_perm(u.x,u.y,0x5410), __byte_perm(u.z,u.w,0x5410));
            *(uint2*)(dsm + A_LO + off) = make_uint2(__byte_perm(u.x,u.y,0x7632), __byte_perm(u.z,u.w,0x7632));
        }
        #pragma unroll
        for (int i = 0; i < 8; i++) {
            int flat = t + i * 512;
            int ch = flat >> 6, px = flat & 63;
            float m = g_mean[b*CH + cb + ch], r = g_rstd[b*CH + cb + ch];
            float val = (xb[(size_t)(cb + ch) * NPIX + px] - m) * r;
            unsigned pk = split_pack(val);
            uint32_t off = (uint32_t)(px * SA + ch) * 2;
            *(unsigned short*)(dsm + B_HI + off) = (unsigned short)pk;
            *(unsigned short*)(dsm + B_LO + off) = (unsigned short)(pk >> 16);
        }
        __syncthreads();

        #pragma unroll
        for (int ks = 0; ks < 4; ks++) {
            const int k0 = ks * 16;
            uint32_t bh[4][2], bl[4][2];
            #pragma unroll
            for (int n = 0; n < 4; n++) {
                uint32_t bo = (uint32_t)((pb + n * 8) * SA + k0 + boff) * 2;
                ldsm_x2(bh[n], smb + B_HI + bo);
                ldsm_x2(bl[n], smb + B_LO + bo);
            }
            #pragma unroll
            for (int m = 0; m < 4; m++) {
                uint32_t ah[4], al[4];
                uint32_t ao = (uint32_t)((rw * 64 + m * 16) * SA + k0 + aoff) * 2;
                ldsm_x4(ah, smb + A_HI + ao);
                ldsm_x4(al, smb + A_LO + ao);
                #pragma unroll
                for (int n = 0; n < 4; n++) {
                    mma16816(acc[m][n], ah, bh[n]);
                    mma16816(acc[m][n], ah, bl[n]);
                    mma16816(acc[m][n], al, bh[n]);
                }
            }
        }
        __syncthreads();
    }

    if (rw < 4) {
        #pragma unroll
        for (int m = 0; m < 4; m++) {
            int row = rw * 64 + m * 16 + gid;
            float zr = 0.f, zr8 = 0.f;
            #pragma unroll
            for (int n = 0; n < 4; n++) {
                int px = pb + n * 8 + 2 * tig;
                float e0 = expf(acc[m][n][0]);
                float e1 = expf(acc[m][n][1]);
                float e2 = expf(acc[m][n][2]);
                float e3 = expf(acc[m][n][3]);
                zr  += e0 + e1;
                zr8 += e2 + e3;
                unsigned p0 = split_pack(e0), p1 = split_pack(e1);
                unsigned p2 = split_pack(e2), p3 = split_pack(e3);
                *(unsigned*)(dsm + EK_HI + ( row      * SV + px) * 2) = __byte_perm(p0, p1, 0x5410);
                *(unsigned*)(dsm + EK_LO + ( row      * SV + px) * 2) = __byte_perm(p0, p1, 0x7632);
                *(unsigned*)(dsm + EK_HI + ((row + 8) * SV + px) * 2) = __byte_perm(p2, p3, 0x5410);
                *(unsigned*)(dsm + EK_LO + ((row + 8) * SV + px) * 2) = __byte_perm(p2, p3, 0x7632);
            }
            zr  += __shfl_xor_sync(0xFFFFFFFFu, zr, 1);
            zr  += __shfl_xor_sync(0xFFFFFFFFu, zr, 2);
            zr8 += __shfl_xor_sync(0xFFFFFFFFu, zr8, 1);
            zr8 += __shfl_xor_sync(0xFFFFFFFFu, zr8, 2);
            if (tig == 0) {
                atomicAdd(&g_Z[b*256 + row],     zr);
                atomicAdd(&g_Z[b*256 + row + 8], zr8);
            }
        }
    } else {
        #pragma unroll
        for (int m = 0; m < 4; m++) {
            int vr = (rw - 4) * 64 + m * 16 + gid;
            #pragma unroll
            for (int n = 0; n < 4; n++) {
                int px = pb + n * 8 + 2 * tig;
                unsigned p0 = split_pack(acc[m][n][0]), p1 = split_pack(acc[m][n][1]);
                unsigned p2 = split_pack(acc[m][n][2]), p3 = split_pack(acc[m][n][3]);
                *(unsigned*)(dsm + V_HI + ( vr      * SV + px) * 2) = __byte_perm(p0, p1, 0x5410);
                *(unsigned*)(dsm + V_LO + ( vr      * SV + px) * 2) = __byte_perm(p0, p1, 0x7632);
                *(unsigned*)(dsm + V_HI + ((vr + 8) * SV + px) * 2) = __byte_perm(p2, p3, 0x5410);
                *(unsigned*)(dsm + V_LO + ((vr + 8) * SV + px) * 2) = __byte_perm(p2, p3, 0x7632);
            }
        }
    }
    __syncthreads();

    {
        const int h  = w & 7;
        const int kb = (w >> 3) * 32;
        const int aoff2 = ((seg & 1) * 8 + lrow) * SV + (seg >> 1) * 8;
        const int boff2 = (l2 & 7) * SV + (l2 >> 3) * 8;
        float sc[2][4][4];
        #pragma unroll
        for (int m = 0; m < 2; m++)
            #pragma unroll
            for (int n = 0; n < 4; n++)
                #pragma unroll
                for (int q = 0; q < 4; q++) sc[m][n][q] = 0.f;

        #pragma unroll
        for (int kk = 0; kk < 2; kk++) {
            const int k0 = kb + kk * 16;
            uint32_t bh2[4][2], bl2[4][2];
            #pragma unroll
            for (int n = 0; n < 4; n++) {
                uint32_t bo = (uint32_t)((h*32 + n*8) * SV + k0 + boff2) * 2;
                ldsm_x2(bh2[n], smb + V_HI + bo);
                ldsm_x2(bl2[n], smb + V_LO + bo);
            }
            #pragma unroll
            for (int m = 0; m < 2; m++) {
                uint32_t ah[4], al[4];
                uint32_t ao = (uint32_t)((h*32 + m*16) * SV + k0 + aoff2) * 2;
                ldsm_x4(ah, smb + EK_HI + ao);
                ldsm_x4(al, smb + EK_LO + ao);
                #pragma unroll
                for (int n = 0; n < 4; n++) {
                    mma16816(sc[m][n], ah, bh2[n]);
                    mma16816(sc[m][n], ah, bl2[n]);
                    mma16816(sc[m][n], al, bh2[n]);
                }
            }
        }
        float* Sb = g_S + (size_t)(b*HEADS + h) * (DH*DH);
        #pragma unroll
        for (int m = 0; m < 2; m++) {
            int d = m*16 + gid;
            #pragma unroll
            for (int n = 0; n < 4; n++) {
                int e = n*8 + 2*tig;
                atomicAdd(&Sb[ d      * DH + e    ], sc[m][n][0]);
                atomicAdd(&Sb[ d      * DH + e + 1], sc[m][n][1]);
                atomicAdd(&Sb[(d + 8) * DH + e    ], sc[m][n][2]);
                atomicAdd(&Sb[(d + 8) * DH + e + 1], sc[m][n][3]);
            }
        }
    }
}

// ---------------- k_wf: finalize ctx, fold into W_out, write split-packed -----------
__global__ __launch_bounds__(256) void k_wf(const float* __restrict__ mem_kv,
                                            const float* __restrict__ w_out) {
    __shared__ float ctxsm[DH*DH];
    __shared__ float wsm[CH*33];
    const int h = blockIdx.x, b = blockIdx.y;
    const int t = threadIdx.x;
    {
        int d  = t >> 3;
        int e0 = (t & 7) * 4;
        float ekm[NMEM];
        float zm = 0.f;
        #pragma unroll
        for (int m = 0; m < NMEM; m++) {
            ekm[m] = expf(mem_kv[(h*DH + d)*NMEM + m]);
            zm += ekm[m];
        }
        float inv = 1.f / (g_Z[(b*HEADS + h)*DH + d] + zm);
        #pragma unroll
        for (int j = 0; j < 4; j++) {
            int e = e0 + j;
            float s = g_S[((size_t)(b*HEADS + h)*DH + d)*DH + e];
            float sm = 0.f;
            #pragma unroll
            for (int m = 0; m < NMEM; m++)
                sm = fmaf(ekm[m], mem_kv[HEADS*DH*NMEM + (h*DH + e)*NMEM + m], sm);
            ctxsm[d*DH + e] = (s + sm) * inv;
        }
    }
    #pragma unroll
    for (int i = 0; i < 8; i++) {
        int idx = t + i * 256;
        int c = idx >> 3, eq = (idx & 7) * 4;
        float4 wv = *(const float4*)(w_out + (size_t)c * CH + h*DH + eq);
        wsm[c*33 + eq+0] = wv.x; wsm[c*33 + eq+1] = wv.y;
        wsm[c*33 + eq+2] = wv.z; wsm[c*33 + eq+3] = wv.w;
    }
    __syncthreads();
    float acc[DH];
    #pragma unroll
    for (int d = 0; d < DH; d++) acc[d] = 0.f;
    for (int e = 0; e < DH; e++) {
        float wv = wsm[t*33 + e];
        #pragma unroll
        for (int d = 0; d < DH; d++)
            acc[d] = fmaf(wv, ctxsm[d*DH + e], acc[d]);
    }
    unsigned* dst = g_wfhl + ((size_t)b*CH + t)*CH + h*DH;
    #pragma unroll
    for (int d = 0; d < DH; d++) dst[d] = split_pack(acc[d]);
}

// ---------------- k_out_mma: 64-px tile, 512 threads ----------------
// smem: XHL hi @0 (33792), lo @33792  ([64 px][264 ch] split bf16)
//       A hi @67584, lo @104448      ([256][72] bf16)
//       Q f32 @141312 (73728)  — aliased after softmax by QHL hi @141312 / lo @175104
#define SX 264
#define OXH 0
#define OXL 33792
#define OAH 67584
#define OAL 104448
#define OQ  141312
#define OQH 141312
#define OQL 175104
#define OUT_SMEM 215040

__global__ __launch_bounds__(512, 1) void k_out_mma(const float* __restrict__ x,
                                                    const float* __restrict__ b_out,
                                                    const float* __restrict__ ln_g,
                                                    float* __restrict__ out) {
    extern __shared__ char dsm[];
    __shared__ float colsum[8][64], colsq[8][64], mcol[64], rcol[64];
    const int b = blockIdx.y, pt = blockIdx.x;
    const int t = threadIdx.x, lane = t & 31, w = t >> 5;
    const uint32_t smb = smem_u32(dsm);
    float* Q = (float*)(dsm + OQ);

    const float* xb = x + (size_t)b * CH * NPIX + (size_t)pt * 64;

    // ---- stage xn once as split-bf16 XHL[px][264] (GEMM1 B + residual source) ----
    #pragma unroll
    for (int i = 0; i < 8; i++) {
        int flat = t + i * 512;          // 0..4095 float4 slots (256 ch x 16)
        int ch = flat >> 4, pxq = (flat & 15) * 4;
        float4 v4 = *(const float4*)(xb + (size_t)ch * NPIX + pxq);
        float m = g_mean[b*CH + ch], r = g_rstd[b*CH + ch];
        float vals[4] = {(v4.x-m)*r, (v4.y-m)*r, (v4.z-m)*r, (v4.w-m)*r};
        #pragma unroll
        for (int j = 0; j < 4; j++) {
            unsigned pk = split_pack(vals[j]);
            uint32_t off = (uint32_t)((pxq + j) * SX + ch) * 2;
            *(unsigned short*)(dsm + OXH + off) = (unsigned short)pk;
            *(unsigned short*)(dsm + OXL + off) = (unsigned short)(pk >> 16);
        }
    }
    __syncthreads();

    const int lrow = lane & 7, seg = lane >> 3;
    const int aoff = ((seg & 1) * 8 + lrow) * SA + (seg >> 1) * 8;
    const int l2 = lane & 15;
    const int boffx = (l2 & 7) * SX + (l2 >> 3) * 8;   // B pattern (stride SX)
    const int gid = lane >> 2, tig = lane & 3;

    const int rw = w & 7;        // 32-row slice
    const int ph = w >> 3;       // px half
    const int pb = ph * 32;

    const uint4* wq4 = (const uint4*)g_whl;
    const uint4* wf4 = (const uint4*)(g_wfhl + (size_t)b * CH * CH);

    float acc[2][4][4];

    #pragma unroll 1
    for (int pass = 0; pass < 2; pass++) {
        const uint4* wsrc = pass ? wf4 : wq4;
        const uint32_t bhb = pass ? OQH : OXH;
        const uint32_t blb = pass ? OQL : OXL;
        #pragma unroll
        for (int m = 0; m < 2; m++)
            #pragma unroll
            for (int n = 0; n < 4; n++)
                #pragma unroll
                for (int q = 0; q < 4; q++) acc[m][n][q] = 0.f;

        #pragma unroll 1
        for (int c = 0; c < 4; c++) {
            // A chunk: 256 rows x 64 ch
            #pragma unroll
            for (int i = 0; i < 8; i++) {
                int flat = t + i * 512;
                int r = flat >> 4, q = flat & 15;
                uint4 u = wsrc[(size_t)r * 64 + c * 16 + q];
                uint32_t off = (uint32_t)r * (SA*2) + q * 8;
                *(uint2*)(dsm + OAH + off) = make_uint2(__byte_perm(u.x,u.y,0x5410), __byte_perm(u.z,u.w,0x5410));
                *(uint2*)(dsm + OAL + off) = make_uint2(__byte_perm(u.x,u.y,0x7632), __byte_perm(u.z,u.w,0x7632));
            }
            __syncthreads();

            #pragma unroll
            for (int ks = 0; ks < 4; ks++) {
                const int k0 = c * 64 + ks * 16;   // ch offset within full-K B tile
                uint32_t bh[4][2], bl[4][2];
                #pragma unroll
                for (int n = 0; n < 4; n++) {
                    uint32_t bo = (uint32_t)((pb + n * 8) * SX + k0 + boffx) * 2;
                    ldsm_x2(bh[n], smb + bhb + bo);
                    ldsm_x2(bl[n], smb + blb + bo);
                }
                #pragma unroll
                for (int m = 0; m < 2; m++) {
                    uint32_t ah[4], al[4];
                    uint32_t ao = (uint32_t)((rw * 32 + m * 16) * SA + ks * 16 + aoff) * 2;
                    ldsm_x4(ah, smb + OAH + ao);
                    ldsm_x4(al, smb + OAL + ao);
                    #pragma unroll
                    for (int n = 0; n < 4; n++) {
                        mma16816(acc[m][n], ah, bh[n]);
                        mma16816(acc[m][n], ah, bl[n]);
                        mma16816(acc[m][n], al, bh[n]);
                    }
                }
            }
            __syncthreads();
        }

        if (pass == 0) {
            // store q fragments -> Q f32
            #pragma unroll
            for (int m = 0; m < 2; m++) {
                int row = rw * 32 + m * 16 + gid;
                #pragma unroll
                for (int n = 0; n < 4; n++) {
                    int px = pb + n * 8 + 2 * tig;
                    Q[ row      * 72 + px    ] = acc[m][n][0];
                    Q[ row      * 72 + px + 1] = acc[m][n][1];
                    Q[(row + 8) * 72 + px    ] = acc[m][n][2];
                    Q[(row + 8) * 72 + px + 1] = acc[m][n][3];
                }
            }
            __syncthreads();
            // softmax: thread = (head, px); read column into regs, sync, write packed QHL
            {
                const int h = t >> 6, p = t & 63;
                float vals[32];
                float mx = -1e30f;
                #pragma unroll
                for (int dd = 0; dd < 32; dd++) {
                    vals[dd] = Q[(h*32 + dd) * 72 + p];
                    mx = fmaxf(mx, vals[dd]);
                }
                float s = 0.f;
                #pragma unroll
                for (int dd = 0; dd < 32; dd++) { vals[dd] = expf(vals[dd] - mx); s += vals[dd]; }
                float inv = SCALE_Q / s;
                __syncthreads();   // all reads of Q done before QHL overwrites
                #pragma unroll
                for (int dd = 0; dd < 32; dd++) {
                    unsigned pk = split_pack(vals[dd] * inv);
                    uint32_t off = (uint32_t)(p * SX + h*32 + dd) * 2;
                    *(unsigned short*)(dsm + OQH + off) = (unsigned short)pk;
                    *(unsigned short*)(dsm + OQL + off) = (unsigned short)(pk >> 16);
                }
            }
            __syncthreads();
        }
    }

    // ---- bias + store y -> Q f32 (QHL no longer needed) ----
    #pragma unroll
    for (int m = 0; m < 2; m++) {
        int row = rw * 32 + m * 16 + gid;
        float bo0 = b_out[row], bo8 = b_out[row + 8];
        #pragma unroll
        for (int n = 0; n < 4; n++) {
            int px = pb + n * 8 + 2 * tig;
            Q[ row      * 72 + px    ] = acc[m][n][0] + bo0;
            Q[ row      * 72 + px + 1] = acc[m][n][1] + bo0;
            Q[(row + 8) * 72 + px    ] = acc[m][n][2] + bo8;
            Q[(row + 8) * 72 + px + 1] = acc[m][n][3] + bo8;
        }
    }
    __syncthreads();

    // ---- channel LayerNorm + residual ----
    const int cb = t >> 6, p = t & 63;
    {
        float ps = 0.f, pq = 0.f;
        #pragma unroll 4
        for (int i = 0; i < 32; i++) {
            float v = Q[(cb + i * 8) * 72 + p];
            ps += v; pq += v * v;
        }
        colsum[cb][p] = ps; colsq[cb][p] = pq;
    }
    __syncthreads();
    if (t < 64) {
        float s = 0.f, q2 = 0.f;
        #pragma unroll
        for (int sg = 0; sg < 8; sg++) { s += colsum[sg][t]; q2 += colsq[sg][t]; }
        float m   = s * (1.f / 256.f);
        float var = q2 * (1.f / 256.f) - m * m;
        mcol[t] = m;
        rcol[t] = rsqrtf(var + LN_EPS);
    }
    __syncthreads();
    float* ob = out + (size_t)b * CH * NPIX + (size_t)pt * 64;
    #pragma unroll 4
    for (int i = 0; i < 32; i++) {
        int c = cb + i * 8;
        uint32_t off = (uint32_t)(p * SX + c) * 2;
        float xh = __bfloat162float(*(__nv_bfloat16*)(dsm + OXH + off));
        float xl = __bfloat162float(*(__nv_bfloat16*)(dsm + OXL + off));
        float v = (Q[c*72 + p] - mcol[p]) * rcol[p] * ln_g[c] + (xh + xl);
        ob[(size_t)c * NPIX + p] = v;
    }
}

// ---------------- launch ----------------
extern "C" void kernel_launch(void* const* d_in, const int* in_sizes, int n_in,
                              void* d_out, int out_size) {
    const float* x      = (const float*)d_in[0];
    const float* w_qkv  = (const float*)d_in[1];
    const float* mem_kv = (const float*)d_in[2];
    const float* w_out  = (const float*)d_in[3];
    const float* b_out  = (const float*)d_in[4];
    const float* ln_g   = (const float*)d_in[5];
    float* out = (float*)d_out;

    cudaFuncSetAttribute(k_kv_mma,  cudaFuncAttributeMaxDynamicSharedMemorySize, KV_SMEM);
    cudaFuncSetAttribute(k_out_mma, cudaFuncAttributeMaxDynamicSharedMemorySize, OUT_SMEM);

    k_zero<<<512, 256>>>();
    k_stats<<<BATCH * CH, 256>>>(x);
    k_wprep<<<768, 256>>>(w_qkv);
    k_kv_mma<<<dim3(NPIX/64, BATCH), 512, KV_SMEM>>>(x);
    k_wf<<<dim3(HEADS, BATCH), 256>>>(mem_kv, w_out);
    k_out_mma<<<dim3(NPIX/64, BATCH), 512, OUT_SMEM>>>(x, b_out, ln_g, out);
}